// round 8
// baseline (speedup 1.0000x reference)
#include <cuda_runtime.h>
#include <cuda_bf16.h>
#include <stdint.h>
#include <math.h>

// Problem dims (fixed by the reference)
#define BATCH  16
#define NSEQ   4096
#define DDIM   512
#define MTOT   (BATCH*NSEQ)          // 65536 rows
#define CHAINS (BATCH*DDIM)          // 8192 scan chains
#define SEGLEN 16
#define NSEG   (NSEQ/SEGLEN)         // 256
#define SEGTOT (NSEG*CHAINS)         // 2097152
#define EPSV   1e-6f
#define N1     (3*DDIM)              // 1536

// GEMM tiling (mma.sync; tcgen05 blocked by compute_100 toolchain)
#define BM 128
#define BN 128
#define KC 16
#define LDT 24                       // padded smem row (bf16): 48B stride
#define TILE_ELEMS (BM*LDT)          // 3072 bf16 per array
#define ARR_BYTES  (TILE_ELEMS*2)    // 6144
#define STAGE_BYTES (4*ARR_BYTES)    // 24576
#define NSTAGE 4
#define HDR 128                      // mbarrier header in dynamic smem
#define SMEM_REQ (HDR + NSTAGE*STAGE_BYTES)  // 98432
#define NCHUNK (DDIM/KC)             // 32
#define NTHREADS 288                 // 8 consumer warps + 1 producer warp

// ---------------- device scratch ----------------
__device__ __nv_bfloat16 g_xhi [MTOT*DDIM];
__device__ __nv_bfloat16 g_xlo [MTOT*DDIM];
__device__ __nv_bfloat16 g_b1hi[N1*DDIM];     // [n][k] transposed W_in|W_gate
__device__ __nv_bfloat16 g_b1lo[N1*DDIM];
__device__ __nv_bfloat16 g_b2hi[DDIM*DDIM];   // [n][k] transposed W_out
__device__ __nv_bfloat16 g_b2lo[DDIM*DDIM];
__device__ float g_su  [MTOT*DDIM];
__device__ float g_lam [MTOT*DDIM];
__device__ float g_gate[MTOT*DDIM];
__device__ float g_h   [MTOT*DDIM];
__device__ __nv_bfloat16 g_hnhi[MTOT*DDIM];
__device__ __nv_bfloat16 g_hnlo[MTOT*DDIM];
__device__ float g_aggA [SEGTOT];
__device__ float g_aggBf[SEGTOT];
__device__ float g_aggBr[SEGTOT];
__device__ float g_cf   [SEGTOT];
__device__ float g_cr   [SEGTOT];

__device__ __forceinline__ float sigm(float x) { return 1.0f / (1.0f + __expf(-x)); }
__device__ __forceinline__ uint32_t pack_bf2(__nv_bfloat16 a, __nv_bfloat16 b) {
    return (uint32_t)__bfloat16_as_ushort(a) | ((uint32_t)__bfloat16_as_ushort(b) << 16);
}

// ---------------- PTX helpers ----------------
__device__ __forceinline__ void mma16816(float* c, const uint32_t* a, const uint32_t* b) {
    asm volatile(
        "mma.sync.aligned.m16n8k16.row.col.f32.bf16.bf16.f32 "
        "{%0,%1,%2,%3}, {%4,%5,%6,%7}, {%8,%9}, {%0,%1,%2,%3};"
        : "+f"(c[0]), "+f"(c[1]), "+f"(c[2]), "+f"(c[3])
        : "r"(a[0]), "r"(a[1]), "r"(a[2]), "r"(a[3]), "r"(b[0]), "r"(b[1]));
}
__device__ __forceinline__ void ldsm4(uint32_t* r, uint32_t addr) {
    asm volatile("ldmatrix.sync.aligned.m8n8.x4.shared.b16 {%0,%1,%2,%3}, [%4];"
                 : "=r"(r[0]), "=r"(r[1]), "=r"(r[2]), "=r"(r[3]) : "r"(addr));
}
__device__ __forceinline__ void cpasync16(uint32_t saddr, const void* g) {
    asm volatile("cp.async.cg.shared.global [%0], [%1], 16;" :: "r"(saddr), "l"(g));
}
__device__ __forceinline__ void mbar_init(uint32_t m, uint32_t cnt) {
    asm volatile("mbarrier.init.shared.b64 [%0], %1;" :: "r"(m), "r"(cnt) : "memory");
}
__device__ __forceinline__ void mbar_wait(uint32_t m, uint32_t parity) {
    asm volatile(
        "{\n\t.reg .pred P;\n\t"
        "LAB_%=:\n\t"
        "mbarrier.try_wait.parity.acquire.cta.shared::cta.b64 P, [%0], %1, 0x989680;\n\t"
        "@!P bra LAB_%=;\n\t}"
        :: "r"(m), "r"(parity) : "memory");
}
__device__ __forceinline__ void mbar_arrive(uint32_t m) {
    asm volatile("mbarrier.arrive.shared.b64 _, [%0];" :: "r"(m) : "memory");
}
// .noinc is REQUIRED: the default form increments pending count at issue and
// decrements at completion (net zero phase progress) -> deadlock with a fixed
// expected-arrival count. .noinc counts completion against the init count.
__device__ __forceinline__ void cp_mbar_arrive_noinc(uint32_t m) {
    asm volatile("cp.async.mbarrier.arrive.noinc.shared::cta.b64 [%0];" :: "r"(m) : "memory");
}

// ================= split conversion kernels =================
__global__ __launch_bounds__(256) void convert_x_kernel(const float* __restrict__ X)
{
    int i = blockIdx.x * 256 + threadIdx.x;            // over float4s
    float4 v = ((const float4*)X)[i];
    __nv_bfloat16 h0 = __float2bfloat16_rn(v.x), h1 = __float2bfloat16_rn(v.y);
    __nv_bfloat16 h2 = __float2bfloat16_rn(v.z), h3 = __float2bfloat16_rn(v.w);
    __nv_bfloat16 l0 = __float2bfloat16_rn(v.x - __bfloat162float(h0));
    __nv_bfloat16 l1 = __float2bfloat16_rn(v.y - __bfloat162float(h1));
    __nv_bfloat16 l2 = __float2bfloat16_rn(v.z - __bfloat162float(h2));
    __nv_bfloat16 l3 = __float2bfloat16_rn(v.w - __bfloat162float(h3));
    uint2 uh; uh.x = pack_bf2(h0, h1); uh.y = pack_bf2(h2, h3);
    uint2 ul; ul.x = pack_bf2(l0, l1); ul.y = pack_bf2(l2, l3);
    ((uint2*)g_xhi)[i] = uh;
    ((uint2*)g_xlo)[i] = ul;
}
__global__ __launch_bounds__(256) void convert_w1_kernel(
    const float* __restrict__ Win, const float* __restrict__ Wg)
{
    int idx = blockIdx.x * 256 + threadIdx.x;          // [0, N1*DDIM)
    int n = idx / DDIM, k = idx % DDIM;
    float w = (n < 2 * DDIM) ? Win[(size_t)k * (2 * DDIM) + n]
                             : Wg [(size_t)k * DDIM + (n - 2 * DDIM)];
    __nv_bfloat16 h = __float2bfloat16_rn(w);
    g_b1hi[idx] = h;
    g_b1lo[idx] = __float2bfloat16_rn(w - __bfloat162float(h));
}
__global__ __launch_bounds__(256) void convert_w2_kernel(const float* __restrict__ Wout)
{
    int idx = blockIdx.x * 256 + threadIdx.x;          // [0, DDIM*DDIM)
    int n = idx / DDIM, k = idx % DDIM;
    float w = Wout[(size_t)k * DDIM + n];
    __nv_bfloat16 h = __float2bfloat16_rn(w);
    g_b2hi[idx] = h;
    g_b2lo[idx] = __float2bfloat16_rn(w - __bfloat162float(h));
}

// =================================================================================
// Warp-specialized mma.sync GEMM.
//   warp 8      : producer — all cp.async loads, signals full[s] via
//                 cp.async.mbarrier.arrive.noinc; gated by empty[s].
//   warps 0..7  : consumers — ldsm + mma only, gated by full[s]; release empty[s].
// No __syncthreads in the mainloop: consumer warps drift, so one warp's ldsm
// burst overlaps other warps' mma streams.
// =================================================================================
template<int MODE>
__global__ void __launch_bounds__(NTHREADS, 2) gemm_tc(
    const __nv_bfloat16* __restrict__ Ahi, const __nv_bfloat16* __restrict__ Alo,
    const __nv_bfloat16* __restrict__ Bhi, const __nv_bfloat16* __restrict__ Blo,
    const float* __restrict__ bias_a, const float* __restrict__ bias_b,
    const float* __restrict__ lbp, float* __restrict__ outp)
{
    extern __shared__ __nv_bfloat16 smem_raw[];
    const uint32_t sb = (uint32_t)__cvta_generic_to_shared(smem_raw);
    const uint32_t tiles = sb + HDR;
    // header: full[0..3] at sb+0..31, empty[0..3] at sb+32..63
    const int tid = threadIdx.x;
    const int lane = tid & 31, wid = tid >> 5;
    const int r0 = blockIdx.y * BM;
    const int c0 = blockIdx.x * BN;

    if (tid == 0) {
        #pragma unroll
        for (int s = 0; s < NSTAGE; s++) {
            mbar_init(sb + s * 8, 32);        // full[s]: 32 producer threads
            mbar_init(sb + 32 + s * 8, 256);  // empty[s]: 256 consumer threads
        }
    }
    __syncthreads();

    if (wid == 8) {
        // ---------------- producer warp ----------------
        for (int c = 0; c < NCHUNK; c++) {
            const int s = c & 3, j = c >> 2;
            const uint32_t st = tiles + (uint32_t)s * STAGE_BYTES;
            const int k0 = c * KC;
            if (j >= 1) mbar_wait(sb + 32 + s * 8, (uint32_t)((j - 1) & 1));
            #pragma unroll
            for (int i = 0; i < 8; i++) {
                int slot = lane + (i << 5);          // 0..255
                int row = slot >> 1, seg = slot & 1;
                uint32_t so = (uint32_t)(row * 48 + seg * 16);
                size_t ga = (size_t)(r0 + row) * DDIM + k0 + seg * 8;
                size_t gb = (size_t)(c0 + row) * DDIM + k0 + seg * 8;
                cpasync16(st + so,                 Ahi + ga);
                cpasync16(st + ARR_BYTES + so,     Alo + ga);
                cpasync16(st + 2 * ARR_BYTES + so, Bhi + gb);
                cpasync16(st + 3 * ARR_BYTES + so, Blo + gb);
            }
            cp_mbar_arrive_noinc(sb + s * 8);   // full[s] when this thread's loads land
        }
        return;
    }

    // ---------------- consumer warps ----------------
    float acc[4][4][4];
    #pragma unroll
    for (int i = 0; i < 4; i++)
        #pragma unroll
        for (int j = 0; j < 4; j++)
            #pragma unroll
            for (int q = 0; q < 4; q++) acc[i][j][q] = 0.0f;

    const int wm = wid >> 2, wn = wid & 3;
    const int sub = lane >> 3, lr = lane & 7;
    const uint32_t boBase = (uint32_t)(wn * 32 + lr + (sub >> 1) * 8) * 48
                          + (uint32_t)(sub & 1) * 16;
    const uint32_t aoBase = (uint32_t)(wm * 64 + lr + (sub & 1) * 8) * 48
                          + (uint32_t)(sub >> 1) * 16;

    for (int c = 0; c < NCHUNK; c++) {
        const int s = c & 3;
        mbar_wait(sb + s * 8, (uint32_t)((c >> 2) & 1));   // full[s]

        const uint32_t st = tiles + (uint32_t)s * STAGE_BYTES;
        const uint32_t sAhi = st;
        const uint32_t sAlo = sAhi + ARR_BYTES;
        const uint32_t sBhi = sAlo + ARR_BYTES;
        const uint32_t sBlo = sBhi + ARR_BYTES;

        uint32_t bhi[4][2], blo[4][2];
        #pragma unroll
        for (int p = 0; p < 2; p++) {
            const uint32_t bo = boBase + (uint32_t)(p * 16) * 48;
            uint32_t t4[4];
            ldsm4(t4, sBhi + bo);
            bhi[2*p][0] = t4[0]; bhi[2*p][1] = t4[1]; bhi[2*p+1][0] = t4[2]; bhi[2*p+1][1] = t4[3];
            ldsm4(t4, sBlo + bo);
            blo[2*p][0] = t4[0]; blo[2*p][1] = t4[1]; blo[2*p+1][0] = t4[2]; blo[2*p+1][1] = t4[3];
        }
        #pragma unroll
        for (int mi = 0; mi < 4; mi++) {
            const uint32_t ao = aoBase + (uint32_t)(mi * 16) * 48;
            uint32_t ahi[4], alo[4];
            ldsm4(ahi, sAhi + ao);
            ldsm4(alo, sAlo + ao);
            #pragma unroll
            for (int ni = 0; ni < 4; ni++) mma16816(acc[mi][ni], ahi, bhi[ni]);
            #pragma unroll
            for (int ni = 0; ni < 4; ni++) mma16816(acc[mi][ni], ahi, blo[ni]);
            #pragma unroll
            for (int ni = 0; ni < 4; ni++) mma16816(acc[mi][ni], alo, bhi[ni]);
        }
        mbar_arrive(sb + 32 + s * 8);                      // empty[s]
    }

    // -------- epilogue --------
    const int g = lane >> 2, t = lane & 3;
    float lb = 0.0f;
    if (MODE == 0) lb = lbp[0];

    #pragma unroll
    for (int mi = 0; mi < 4; mi++) {
        const int m0 = r0 + wm * 64 + mi * 16 + g;
        #pragma unroll
        for (int ni = 0; ni < 4; ni++) {
            const int nc = c0 + wn * 32 + ni * 8 + t * 2;
            float p0 = acc[mi][ni][0], p1 = acc[mi][ni][1];
            float p2 = acc[mi][ni][2], p3 = acc[mi][ni][3];
            if (MODE == 1) {
                const float b0 = bias_a[nc], b1 = bias_a[nc + 1];
                *(float2*)&outp[(size_t)m0 * DDIM + nc]       = make_float2(p0 + b0, p1 + b1);
                *(float2*)&outp[(size_t)(m0+8) * DDIM + nc]   = make_float2(p2 + b0, p3 + b1);
            } else {
                const int reg = nc >> 9;           // 0=u, 1=f, 2=gate
                const int lc = nc & 511;
                float b0, b1; float* dst;
                if (reg < 2) { b0 = bias_a[nc]; b1 = bias_a[nc + 1]; }
                else         { b0 = bias_b[lc]; b1 = bias_b[lc + 1]; }
                p0 += b0; p1 += b1; p2 += b0; p3 += b1;
                float o0, o1, o2, o3;
                if (reg == 0) {
                    o0 = p0 * sigm(p0); o1 = p1 * sigm(p1);
                    o2 = p2 * sigm(p2); o3 = p3 * sigm(p3);
                    dst = g_su;
                } else if (reg == 1) {
                    const float w = 1.0f - lb;
                    o0 = lb + w * sigm(p0); o1 = lb + w * sigm(p1);
                    o2 = lb + w * sigm(p2); o3 = lb + w * sigm(p3);
                    dst = g_lam;
                } else {
                    o0 = sigm(p0); o1 = sigm(p1); o2 = sigm(p2); o3 = sigm(p3);
                    dst = g_gate;
                }
                *(float2*)&dst[(size_t)m0 * DDIM + lc]     = make_float2(o0, o1);
                *(float2*)&dst[(size_t)(m0+8) * DDIM + lc] = make_float2(o2, o3);
            }
        }
    }
}

// ================= scan path =================
__global__ __launch_bounds__(256) void scan_phase1()
{
    int tt = blockIdx.x * blockDim.x + threadIdx.x;
    int chain = tt % CHAINS;
    int seg   = tt / CHAINS;
    int d = chain % DDIM, b = chain / DDIM;
    size_t base = ((size_t)(b * NSEQ + seg * SEGLEN)) * DDIM + d;

    float l[SEGLEN], v[SEGLEN];
    #pragma unroll
    for (int i = 0; i < SEGLEN; i++) {
        size_t idx = base + (size_t)i * DDIM;
        float li = g_lam[idx];
        float si = g_su[idx];
        l[i] = li;
        v[i] = (1.0f - li) * si;
    }
    float h = 0.0f, P = 1.0f;
    #pragma unroll
    for (int i = 0; i < SEGLEN; i++) { h = l[i] * h + v[i]; P *= l[i]; }
    float hr = 0.0f;
    #pragma unroll
    for (int i = SEGLEN - 1; i >= 0; i--) hr = l[i] * hr + v[i];

    size_t aidx = (size_t)seg * CHAINS + chain;
    g_aggA [aidx] = P;
    g_aggBf[aidx] = h;
    g_aggBr[aidx] = hr;
}
__global__ __launch_bounds__(256) void scan_phase2()
{
    int c = blockIdx.x * blockDim.x + threadIdx.x;
    float carry = 0.0f;
    #pragma unroll 8
    for (int s = 0; s < NSEG; s++) {
        size_t a = (size_t)s * CHAINS + c;
        g_cf[a] = carry;
        carry = g_aggA[a] * carry + g_aggBf[a];
    }
    carry = 0.0f;
    #pragma unroll 8
    for (int s = NSEG - 1; s >= 0; s--) {
        size_t a = (size_t)s * CHAINS + c;
        g_cr[a] = carry;
        carry = g_aggA[a] * carry + g_aggBr[a];
    }
}
__global__ __launch_bounds__(256) void scan_phase3()
{
    int tt = blockIdx.x * blockDim.x + threadIdx.x;
    int chain = tt % CHAINS;
    int seg   = tt / CHAINS;
    int d = chain % DDIM, b = chain / DDIM;
    size_t base = ((size_t)(b * NSEQ + seg * SEGLEN)) * DDIM + d;
    size_t aidx = (size_t)seg * CHAINS + chain;
    float cf = g_cf[aidx];
    float cr = g_cr[aidx];

    float l[SEGLEN], v[SEGLEN], hf[SEGLEN];
    #pragma unroll
    for (int i = 0; i < SEGLEN; i++) {
        size_t idx = base + (size_t)i * DDIM;
        float li = g_lam[idx];
        float si = g_su[idx];
        l[i] = li;
        v[i] = (1.0f - li) * si;
    }
    float h = cf;
    #pragma unroll
    for (int i = 0; i < SEGLEN; i++) { h = l[i] * h + v[i]; hf[i] = h; }
    float hr = cr;
    #pragma unroll
    for (int i = SEGLEN - 1; i >= 0; i--) {
        hr = l[i] * hr + v[i];
        g_h[base + (size_t)i * DDIM] = hf[i] + hr;
    }
}
__global__ __launch_bounds__(256) void rms_gate_kernel()
{
    int warp = threadIdx.x >> 5, lane = threadIdx.x & 31;
    int row = blockIdx.x * 8 + warp;
    size_t base = (size_t)row * DDIM + lane * 4;

    float4 hv[4];
    float ss = 0.0f;
    #pragma unroll
    for (int j = 0; j < 4; j++) {
        hv[j] = *(const float4*)&g_h[base + j * 128];
        ss += hv[j].x * hv[j].x + hv[j].y * hv[j].y + hv[j].z * hv[j].z + hv[j].w * hv[j].w;
    }
    #pragma unroll
    for (int o = 16; o > 0; o >>= 1) ss += __shfl_xor_sync(0xffffffff, ss, o);
    float scale = rsqrtf(ss * (1.0f / DDIM) + EPSV);

    #pragma unroll
    for (int j = 0; j < 4; j++) {
        float4 gv = *(const float4*)&g_gate[base + j * 128];
        float o0 = hv[j].x * scale * gv.x;
        float o1 = hv[j].y * scale * gv.y;
        float o2 = hv[j].z * scale * gv.z;
        float o3 = hv[j].w * scale * gv.w;
        __nv_bfloat16 h0 = __float2bfloat16_rn(o0), h1 = __float2bfloat16_rn(o1);
        __nv_bfloat16 h2 = __float2bfloat16_rn(o2), h3 = __float2bfloat16_rn(o3);
        __nv_bfloat16 l0 = __float2bfloat16_rn(o0 - __bfloat162float(h0));
        __nv_bfloat16 l1 = __float2bfloat16_rn(o1 - __bfloat162float(h1));
        __nv_bfloat16 l2 = __float2bfloat16_rn(o2 - __bfloat162float(h2));
        __nv_bfloat16 l3 = __float2bfloat16_rn(o3 - __bfloat162float(h3));
        uint2 uh; uh.x = pack_bf2(h0, h1); uh.y = pack_bf2(h2, h3);
        uint2 ul; ul.x = pack_bf2(l0, l1); ul.y = pack_bf2(l2, l3);
        *(uint2*)&g_hnhi[base + j * 128] = uh;
        *(uint2*)&g_hnlo[base + j * 128] = ul;
    }
}

// ================= launch =================
extern "C" void kernel_launch(void* const* d_in, const int* in_sizes, int n_in,
                              void* d_out, int out_size)
{
    const float* x    = (const float*)d_in[0];
    const float* lb   = (const float*)d_in[1];
    const float* Win  = (const float*)d_in[2];
    const float* bin  = (const float*)d_in[3];
    const float* Wg   = (const float*)d_in[4];
    const float* bg   = (const float*)d_in[5];
    const float* Wout = (const float*)d_in[6];
    const float* bout = (const float*)d_in[7];
    float* out = (float*)d_out;

    __nv_bfloat16 *xhi, *xlo, *b1hi, *b1lo, *b2hi, *b2lo, *hnhi, *hnlo;
    cudaGetSymbolAddress((void**)&xhi,  g_xhi);
    cudaGetSymbolAddress((void**)&xlo,  g_xlo);
    cudaGetSymbolAddress((void**)&b1hi, g_b1hi);
    cudaGetSymbolAddress((void**)&b1lo, g_b1lo);
    cudaGetSymbolAddress((void**)&b2hi, g_b2hi);
    cudaGetSymbolAddress((void**)&b2lo, g_b2lo);
    cudaGetSymbolAddress((void**)&hnhi, g_hnhi);
    cudaGetSymbolAddress((void**)&hnlo, g_hnlo);

    cudaFuncSetAttribute(gemm_tc<0>, cudaFuncAttributeMaxDynamicSharedMemorySize, SMEM_REQ);
    cudaFuncSetAttribute(gemm_tc<1>, cudaFuncAttributeMaxDynamicSharedMemorySize, SMEM_REQ);

    convert_x_kernel<<<(MTOT * DDIM / 4) / 256, 256>>>(x);
    convert_w1_kernel<<<(N1 * DDIM) / 256, 256>>>(Win, Wg);
    convert_w2_kernel<<<(DDIM * DDIM) / 256, 256>>>(Wout);

    dim3 g1(N1 / BN, MTOT / BM);           // (12, 512)
    gemm_tc<0><<<g1, NTHREADS, SMEM_REQ>>>(xhi, xlo, b1hi, b1lo, bin, bg, lb, nullptr);

    scan_phase1<<<SEGTOT / 256, 256>>>();
    scan_phase2<<<CHAINS / 256, 256>>>();
    scan_phase3<<<SEGTOT / 256, 256>>>();
    rms_gate_kernel<<<MTOT / 8, 256>>>();

    dim3 g2(DDIM / BN, MTOT / BM);         // (4, 512)
    gemm_tc<1><<<g2, NTHREADS, SMEM_REQ>>>(hnhi, hnlo, b2hi, b2lo, bout, nullptr, nullptr, out);
}

// round 10
// speedup vs baseline: 1.0033x; 1.0033x over previous
#include <cuda_runtime.h>
#include <cuda_bf16.h>
#include <stdint.h>
#include <math.h>

// Problem dims (fixed by the reference)
#define BATCH  16
#define NSEQ   4096
#define DDIM   512
#define MTOT   (BATCH*NSEQ)          // 65536 rows
#define CHAINS (BATCH*DDIM)          // 8192 scan chains
#define SEGLEN 16
#define NSEG   (NSEQ/SEGLEN)         // 256
#define SEGTOT (NSEG*CHAINS)         // 2097152
#define EPSV   1e-6f
#define N1     (3*DDIM)              // 1536

// GEMM tiling (mma.sync; tcgen05 blocked by compute_100 toolchain)
#define BM 128
#define BN 128
#define KC 16
#define LDT 24                       // padded smem row (bf16): 48B stride
#define TILE_ELEMS (BM*LDT)          // 3072 bf16 per array
#define ARR_BYTES  (TILE_ELEMS*2)    // 6144
#define STAGE_BYTES (4*ARR_BYTES)    // 24576
#define NSTAGE 4
#define HDR 128                      // mbarrier header in dynamic smem
#define SMEM_REQ (HDR + NSTAGE*STAGE_BYTES)  // 98432
#define NCHUNK (DDIM/KC)             // 32
#define NTHREADS 288                 // 8 consumer warps + 1 producer warp

// ---------------- device scratch ----------------
__device__ __nv_bfloat16 g_xhi [MTOT*DDIM];
__device__ __nv_bfloat16 g_xlo [MTOT*DDIM];
__device__ __nv_bfloat16 g_b1hi[N1*DDIM];     // [n][k] transposed W_in|W_gate
__device__ __nv_bfloat16 g_b1lo[N1*DDIM];
__device__ __nv_bfloat16 g_b2hi[DDIM*DDIM];   // [n][k] transposed W_out
__device__ __nv_bfloat16 g_b2lo[DDIM*DDIM];
__device__ float g_su  [MTOT*DDIM];
__device__ float g_lam [MTOT*DDIM];
__device__ float g_gate[MTOT*DDIM];
__device__ float g_h   [MTOT*DDIM];
__device__ __nv_bfloat16 g_hnhi[MTOT*DDIM];
__device__ __nv_bfloat16 g_hnlo[MTOT*DDIM];
__device__ float g_aggA [SEGTOT];
__device__ float g_aggBf[SEGTOT];
__device__ float g_aggBr[SEGTOT];
__device__ float g_cf   [SEGTOT];
__device__ float g_cr   [SEGTOT];

__device__ __forceinline__ float sigm(float x) { return 1.0f / (1.0f + __expf(-x)); }
__device__ __forceinline__ uint32_t pack_bf2(__nv_bfloat16 a, __nv_bfloat16 b) {
    return (uint32_t)__bfloat16_as_ushort(a) | ((uint32_t)__bfloat16_as_ushort(b) << 16);
}

// ---------------- PTX helpers ----------------
__device__ __forceinline__ void mma16816(float* c, const uint32_t* a, const uint32_t* b) {
    asm volatile(
        "mma.sync.aligned.m16n8k16.row.col.f32.bf16.bf16.f32 "
        "{%0,%1,%2,%3}, {%4,%5,%6,%7}, {%8,%9}, {%0,%1,%2,%3};"
        : "+f"(c[0]), "+f"(c[1]), "+f"(c[2]), "+f"(c[3])
        : "r"(a[0]), "r"(a[1]), "r"(a[2]), "r"(a[3]), "r"(b[0]), "r"(b[1]));
}
__device__ __forceinline__ void ldsm4(uint32_t* r, uint32_t addr) {
    asm volatile("ldmatrix.sync.aligned.m8n8.x4.shared.b16 {%0,%1,%2,%3}, [%4];"
                 : "=r"(r[0]), "=r"(r[1]), "=r"(r[2]), "=r"(r[3]) : "r"(addr));
}
__device__ __forceinline__ void cpasync16(uint32_t saddr, const void* g) {
    asm volatile("cp.async.cg.shared.global [%0], [%1], 16;" :: "r"(saddr), "l"(g));
}
__device__ __forceinline__ void mbar_init(uint32_t m, uint32_t cnt) {
    asm volatile("mbarrier.init.shared.b64 [%0], %1;" :: "r"(m), "r"(cnt) : "memory");
}
__device__ __forceinline__ void mbar_wait(uint32_t m, uint32_t parity) {
    asm volatile(
        "{\n\t.reg .pred P;\n\t"
        "LAB_%=:\n\t"
        "mbarrier.try_wait.parity.acquire.cta.shared::cta.b64 P, [%0], %1, 0x989680;\n\t"
        "@!P bra LAB_%=;\n\t}"
        :: "r"(m), "r"(parity) : "memory");
}
__device__ __forceinline__ void mbar_arrive(uint32_t m) {
    asm volatile("mbarrier.arrive.shared.b64 _, [%0];" :: "r"(m) : "memory");
}
// .noinc is REQUIRED: the default form increments pending count at issue and
// decrements at completion (net zero phase progress) -> deadlock with a fixed
// expected-arrival count. .noinc counts completion against the init count.
__device__ __forceinline__ void cp_mbar_arrive_noinc(uint32_t m) {
    asm volatile("cp.async.mbarrier.arrive.noinc.shared::cta.b64 [%0];" :: "r"(m) : "memory");
}

// ================= split conversion kernels =================
__global__ __launch_bounds__(256) void convert_x_kernel(const float* __restrict__ X)
{
    int i = blockIdx.x * 256 + threadIdx.x;            // over float4s
    float4 v = ((const float4*)X)[i];
    __nv_bfloat16 h0 = __float2bfloat16_rn(v.x), h1 = __float2bfloat16_rn(v.y);
    __nv_bfloat16 h2 = __float2bfloat16_rn(v.z), h3 = __float2bfloat16_rn(v.w);
    __nv_bfloat16 l0 = __float2bfloat16_rn(v.x - __bfloat162float(h0));
    __nv_bfloat16 l1 = __float2bfloat16_rn(v.y - __bfloat162float(h1));
    __nv_bfloat16 l2 = __float2bfloat16_rn(v.z - __bfloat162float(h2));
    __nv_bfloat16 l3 = __float2bfloat16_rn(v.w - __bfloat162float(h3));
    uint2 uh; uh.x = pack_bf2(h0, h1); uh.y = pack_bf2(h2, h3);
    uint2 ul; ul.x = pack_bf2(l0, l1); ul.y = pack_bf2(l2, l3);
    ((uint2*)g_xhi)[i] = uh;
    ((uint2*)g_xlo)[i] = ul;
}
__global__ __launch_bounds__(256) void convert_w1_kernel(
    const float* __restrict__ Win, const float* __restrict__ Wg)
{
    int idx = blockIdx.x * 256 + threadIdx.x;          // [0, N1*DDIM)
    int n = idx / DDIM, k = idx % DDIM;
    float w = (n < 2 * DDIM) ? Win[(size_t)k * (2 * DDIM) + n]
                             : Wg [(size_t)k * DDIM + (n - 2 * DDIM)];
    __nv_bfloat16 h = __float2bfloat16_rn(w);
    g_b1hi[idx] = h;
    g_b1lo[idx] = __float2bfloat16_rn(w - __bfloat162float(h));
}
__global__ __launch_bounds__(256) void convert_w2_kernel(const float* __restrict__ Wout)
{
    int idx = blockIdx.x * 256 + threadIdx.x;          // [0, DDIM*DDIM)
    int n = idx / DDIM, k = idx % DDIM;
    float w = Wout[(size_t)k * DDIM + n];
    __nv_bfloat16 h = __float2bfloat16_rn(w);
    g_b2hi[idx] = h;
    g_b2lo[idx] = __float2bfloat16_rn(w - __bfloat162float(h));
}

// =================================================================================
// Warp-specialized mma.sync GEMM.
//   warp 8      : producer — all cp.async loads, signals full[s] via
//                 cp.async.mbarrier.arrive.noinc; gated by empty[s].
//   warps 0..7  : consumers — ldsm + mma only, gated by full[s]; release empty[s].
// No __syncthreads in the mainloop: consumer warps drift, so one warp's ldsm
// burst overlaps other warps' mma streams.
// =================================================================================
template<int MODE>
__global__ void __launch_bounds__(NTHREADS, 2) gemm_tc(
    const __nv_bfloat16* __restrict__ Ahi, const __nv_bfloat16* __restrict__ Alo,
    const __nv_bfloat16* __restrict__ Bhi, const __nv_bfloat16* __restrict__ Blo,
    const float* __restrict__ bias_a, const float* __restrict__ bias_b,
    const float* __restrict__ lbp, float* __restrict__ outp)
{
    extern __shared__ __nv_bfloat16 smem_raw[];
    const uint32_t sb = (uint32_t)__cvta_generic_to_shared(smem_raw);
    const uint32_t tiles = sb + HDR;
    // header: full[0..3] at sb+0..31, empty[0..3] at sb+32..63
    const int tid = threadIdx.x;
    const int lane = tid & 31, wid = tid >> 5;
    const int r0 = blockIdx.y * BM;
    const int c0 = blockIdx.x * BN;

    if (tid == 0) {
        #pragma unroll
        for (int s = 0; s < NSTAGE; s++) {
            mbar_init(sb + s * 8, 32);        // full[s]: 32 producer threads
            mbar_init(sb + 32 + s * 8, 256);  // empty[s]: 256 consumer threads
        }
    }
    __syncthreads();

    if (wid == 8) {
        // ---------------- producer warp ----------------
        for (int c = 0; c < NCHUNK; c++) {
            const int s = c & 3, j = c >> 2;
            const uint32_t st = tiles + (uint32_t)s * STAGE_BYTES;
            const int k0 = c * KC;
            if (j >= 1) mbar_wait(sb + 32 + s * 8, (uint32_t)((j - 1) & 1));
            #pragma unroll
            for (int i = 0; i < 8; i++) {
                int slot = lane + (i << 5);          // 0..255
                int row = slot >> 1, seg = slot & 1;
                uint32_t so = (uint32_t)(row * 48 + seg * 16);
                size_t ga = (size_t)(r0 + row) * DDIM + k0 + seg * 8;
                size_t gb = (size_t)(c0 + row) * DDIM + k0 + seg * 8;
                cpasync16(st + so,                 Ahi + ga);
                cpasync16(st + ARR_BYTES + so,     Alo + ga);
                cpasync16(st + 2 * ARR_BYTES + so, Bhi + gb);
                cpasync16(st + 3 * ARR_BYTES + so, Blo + gb);
            }
            cp_mbar_arrive_noinc(sb + s * 8);   // full[s] when this thread's loads land
        }
        return;
    }

    // ---------------- consumer warps ----------------
    float acc[4][4][4];
    #pragma unroll
    for (int i = 0; i < 4; i++)
        #pragma unroll
        for (int j = 0; j < 4; j++)
            #pragma unroll
            for (int q = 0; q < 4; q++) acc[i][j][q] = 0.0f;

    const int wm = wid >> 2, wn = wid & 3;
    const int sub = lane >> 3, lr = lane & 7;
    const uint32_t boBase = (uint32_t)(wn * 32 + lr + (sub >> 1) * 8) * 48
                          + (uint32_t)(sub & 1) * 16;
    const uint32_t aoBase = (uint32_t)(wm * 64 + lr + (sub & 1) * 8) * 48
                          + (uint32_t)(sub >> 1) * 16;

    for (int c = 0; c < NCHUNK; c++) {
        const int s = c & 3;
        mbar_wait(sb + s * 8, (uint32_t)((c >> 2) & 1));   // full[s]

        const uint32_t st = tiles + (uint32_t)s * STAGE_BYTES;
        const uint32_t sAhi = st;
        const uint32_t sAlo = sAhi + ARR_BYTES;
        const uint32_t sBhi = sAlo + ARR_BYTES;
        const uint32_t sBlo = sBhi + ARR_BYTES;

        uint32_t bhi[4][2], blo[4][2];
        #pragma unroll
        for (int p = 0; p < 2; p++) {
            const uint32_t bo = boBase + (uint32_t)(p * 16) * 48;
            uint32_t t4[4];
            ldsm4(t4, sBhi + bo);
            bhi[2*p][0] = t4[0]; bhi[2*p][1] = t4[1]; bhi[2*p+1][0] = t4[2]; bhi[2*p+1][1] = t4[3];
            ldsm4(t4, sBlo + bo);
            blo[2*p][0] = t4[0]; blo[2*p][1] = t4[1]; blo[2*p+1][0] = t4[2]; blo[2*p+1][1] = t4[3];
        }
        #pragma unroll
        for (int mi = 0; mi < 4; mi++) {
            const uint32_t ao = aoBase + (uint32_t)(mi * 16) * 48;
            uint32_t ahi[4], alo[4];
            ldsm4(ahi, sAhi + ao);
            ldsm4(alo, sAlo + ao);
            #pragma unroll
            for (int ni = 0; ni < 4; ni++) mma16816(acc[mi][ni], ahi, bhi[ni]);
            #pragma unroll
            for (int ni = 0; ni < 4; ni++) mma16816(acc[mi][ni], ahi, blo[ni]);
            #pragma unroll
            for (int ni = 0; ni < 4; ni++) mma16816(acc[mi][ni], alo, bhi[ni]);
        }
        mbar_arrive(sb + 32 + s * 8);                      // empty[s]
    }

    // -------- epilogue --------
    const int g = lane >> 2, t = lane & 3;
    float lb = 0.0f;
    if (MODE == 0) lb = lbp[0];

    #pragma unroll
    for (int mi = 0; mi < 4; mi++) {
        const int m0 = r0 + wm * 64 + mi * 16 + g;
        #pragma unroll
        for (int ni = 0; ni < 4; ni++) {
            const int nc = c0 + wn * 32 + ni * 8 + t * 2;
            float p0 = acc[mi][ni][0], p1 = acc[mi][ni][1];
            float p2 = acc[mi][ni][2], p3 = acc[mi][ni][3];
            if (MODE == 1) {
                const float b0 = bias_a[nc], b1 = bias_a[nc + 1];
                *(float2*)&outp[(size_t)m0 * DDIM + nc]       = make_float2(p0 + b0, p1 + b1);
                *(float2*)&outp[(size_t)(m0+8) * DDIM + nc]   = make_float2(p2 + b0, p3 + b1);
            } else {
                const int reg = nc >> 9;           // 0=u, 1=f, 2=gate
                const int lc = nc & 511;
                float b0, b1; float* dst;
                if (reg < 2) { b0 = bias_a[nc]; b1 = bias_a[nc + 1]; }
                else         { b0 = bias_b[lc]; b1 = bias_b[lc + 1]; }
                p0 += b0; p1 += b1; p2 += b0; p3 += b1;
                float o0, o1, o2, o3;
                if (reg == 0) {
                    o0 = p0 * sigm(p0); o1 = p1 * sigm(p1);
                    o2 = p2 * sigm(p2); o3 = p3 * sigm(p3);
                    dst = g_su;
                } else if (reg == 1) {
                    const float w = 1.0f - lb;
                    o0 = lb + w * sigm(p0); o1 = lb + w * sigm(p1);
                    o2 = lb + w * sigm(p2); o3 = lb + w * sigm(p3);
                    dst = g_lam;
                } else {
                    o0 = sigm(p0); o1 = sigm(p1); o2 = sigm(p2); o3 = sigm(p3);
                    dst = g_gate;
                }
                *(float2*)&dst[(size_t)m0 * DDIM + lc]     = make_float2(o0, o1);
                *(float2*)&dst[(size_t)(m0+8) * DDIM + lc] = make_float2(o2, o3);
            }
        }
    }
}

// ================= scan path =================
__global__ __launch_bounds__(256) void scan_phase1()
{
    int tt = blockIdx.x * blockDim.x + threadIdx.x;
    int chain = tt % CHAINS;
    int seg   = tt / CHAINS;
    int d = chain % DDIM, b = chain / DDIM;
    size_t base = ((size_t)(b * NSEQ + seg * SEGLEN)) * DDIM + d;

    float l[SEGLEN], v[SEGLEN];
    #pragma unroll
    for (int i = 0; i < SEGLEN; i++) {
        size_t idx = base + (size_t)i * DDIM;
        float li = g_lam[idx];
        float si = g_su[idx];
        l[i] = li;
        v[i] = (1.0f - li) * si;
    }
    float h = 0.0f, P = 1.0f;
    #pragma unroll
    for (int i = 0; i < SEGLEN; i++) { h = l[i] * h + v[i]; P *= l[i]; }
    float hr = 0.0f;
    #pragma unroll
    for (int i = SEGLEN - 1; i >= 0; i--) hr = l[i] * hr + v[i];

    size_t aidx = (size_t)seg * CHAINS + chain;
    g_aggA [aidx] = P;
    g_aggBf[aidx] = h;
    g_aggBr[aidx] = hr;
}
__global__ __launch_bounds__(256) void scan_phase2()
{
    int c = blockIdx.x * blockDim.x + threadIdx.x;
    float carry = 0.0f;
    #pragma unroll 8
    for (int s = 0; s < NSEG; s++) {
        size_t a = (size_t)s * CHAINS + c;
        g_cf[a] = carry;
        carry = g_aggA[a] * carry + g_aggBf[a];
    }
    carry = 0.0f;
    #pragma unroll 8
    for (int s = NSEG - 1; s >= 0; s--) {
        size_t a = (size_t)s * CHAINS + c;
        g_cr[a] = carry;
        carry = g_aggA[a] * carry + g_aggBr[a];
    }
}
__global__ __launch_bounds__(256) void scan_phase3()
{
    int tt = blockIdx.x * blockDim.x + threadIdx.x;
    int chain = tt % CHAINS;
    int seg   = tt / CHAINS;
    int d = chain % DDIM, b = chain / DDIM;
    size_t base = ((size_t)(b * NSEQ + seg * SEGLEN)) * DDIM + d;
    size_t aidx = (size_t)seg * CHAINS + chain;
    float cf = g_cf[aidx];
    float cr = g_cr[aidx];

    float l[SEGLEN], v[SEGLEN], hf[SEGLEN];
    #pragma unroll
    for (int i = 0; i < SEGLEN; i++) {
        size_t idx = base + (size_t)i * DDIM;
        float li = g_lam[idx];
        float si = g_su[idx];
        l[i] = li;
        v[i] = (1.0f - li) * si;
    }
    float h = cf;
    #pragma unroll
    for (int i = 0; i < SEGLEN; i++) { h = l[i] * h + v[i]; hf[i] = h; }
    float hr = cr;
    #pragma unroll
    for (int i = SEGLEN - 1; i >= 0; i--) {
        hr = l[i] * hr + v[i];
        g_h[base + (size_t)i * DDIM] = hf[i] + hr;
    }
}
__global__ __launch_bounds__(256) void rms_gate_kernel()
{
    int warp = threadIdx.x >> 5, lane = threadIdx.x & 31;
    int row = blockIdx.x * 8 + warp;
    size_t base = (size_t)row * DDIM + lane * 4;

    float4 hv[4];
    float ss = 0.0f;
    #pragma unroll
    for (int j = 0; j < 4; j++) {
        hv[j] = *(const float4*)&g_h[base + j * 128];
        ss += hv[j].x * hv[j].x + hv[j].y * hv[j].y + hv[j].z * hv[j].z + hv[j].w * hv[j].w;
    }
    #pragma unroll
    for (int o = 16; o > 0; o >>= 1) ss += __shfl_xor_sync(0xffffffff, ss, o);
    float scale = rsqrtf(ss * (1.0f / DDIM) + EPSV);

    #pragma unroll
    for (int j = 0; j < 4; j++) {
        float4 gv = *(const float4*)&g_gate[base + j * 128];
        float o0 = hv[j].x * scale * gv.x;
        float o1 = hv[j].y * scale * gv.y;
        float o2 = hv[j].z * scale * gv.z;
        float o3 = hv[j].w * scale * gv.w;
        __nv_bfloat16 h0 = __float2bfloat16_rn(o0), h1 = __float2bfloat16_rn(o1);
        __nv_bfloat16 h2 = __float2bfloat16_rn(o2), h3 = __float2bfloat16_rn(o3);
        __nv_bfloat16 l0 = __float2bfloat16_rn(o0 - __bfloat162float(h0));
        __nv_bfloat16 l1 = __float2bfloat16_rn(o1 - __bfloat162float(h1));
        __nv_bfloat16 l2 = __float2bfloat16_rn(o2 - __bfloat162float(h2));
        __nv_bfloat16 l3 = __float2bfloat16_rn(o3 - __bfloat162float(h3));
        uint2 uh; uh.x = pack_bf2(h0, h1); uh.y = pack_bf2(h2, h3);
        uint2 ul; ul.x = pack_bf2(l0, l1); ul.y = pack_bf2(l2, l3);
        *(uint2*)&g_hnhi[base + j * 128] = uh;
        *(uint2*)&g_hnlo[base + j * 128] = ul;
    }
}

// ================= launch =================
extern "C" void kernel_launch(void* const* d_in, const int* in_sizes, int n_in,
                              void* d_out, int out_size)
{
    const float* x    = (const float*)d_in[0];
    const float* lb   = (const float*)d_in[1];
    const float* Win  = (const float*)d_in[2];
    const float* bin  = (const float*)d_in[3];
    const float* Wg   = (const float*)d_in[4];
    const float* bg   = (const float*)d_in[5];
    const float* Wout = (const float*)d_in[6];
    const float* bout = (const float*)d_in[7];
    float* out = (float*)d_out;

    __nv_bfloat16 *xhi, *xlo, *b1hi, *b1lo, *b2hi, *b2lo, *hnhi, *hnlo;
    cudaGetSymbolAddress((void**)&xhi,  g_xhi);
    cudaGetSymbolAddress((void**)&xlo,  g_xlo);
    cudaGetSymbolAddress((void**)&b1hi, g_b1hi);
    cudaGetSymbolAddress((void**)&b1lo, g_b1lo);
    cudaGetSymbolAddress((void**)&b2hi, g_b2hi);
    cudaGetSymbolAddress((void**)&b2lo, g_b2lo);
    cudaGetSymbolAddress((void**)&hnhi, g_hnhi);
    cudaGetSymbolAddress((void**)&hnlo, g_hnlo);

    cudaFuncSetAttribute(gemm_tc<0>, cudaFuncAttributeMaxDynamicSharedMemorySize, SMEM_REQ);
    cudaFuncSetAttribute(gemm_tc<1>, cudaFuncAttributeMaxDynamicSharedMemorySize, SMEM_REQ);

    convert_x_kernel<<<(MTOT * DDIM / 4) / 256, 256>>>(x);
    convert_w1_kernel<<<(N1 * DDIM) / 256, 256>>>(Win, Wg);
    convert_w2_kernel<<<(DDIM * DDIM) / 256, 256>>>(Wout);

    dim3 g1(N1 / BN, MTOT / BM);           // (12, 512)
    gemm_tc<0><<<g1, NTHREADS, SMEM_REQ>>>(xhi, xlo, b1hi, b1lo, bin, bg, lb, nullptr);

    scan_phase1<<<SEGTOT / 256, 256>>>();
    scan_phase2<<<CHAINS / 256, 256>>>();
    scan_phase3<<<SEGTOT / 256, 256>>>();
    rms_gate_kernel<<<MTOT / 8, 256>>>();

    dim3 g2(DDIM / BN, MTOT / BM);         // (4, 512)
    gemm_tc<1><<<g2, NTHREADS, SMEM_REQ>>>(hnhi, hnlo, b2hi, b2lo, bout, nullptr, nullptr, out);
}

// round 11
// speedup vs baseline: 1.4239x; 1.4193x over previous
#include <cuda_runtime.h>
#include <cuda_fp16.h>
#include <stdint.h>
#include <math.h>

// Problem dims (fixed by the reference)
#define BATCH  16
#define NSEQ   4096
#define DDIM   512
#define MTOT   (BATCH*NSEQ)          // 65536 rows
#define CHAINS (BATCH*DDIM)          // 8192 scan chains
#define SEGLEN 16
#define NSEG   (NSEQ/SEGLEN)         // 256
#define SEGTOT (NSEG*CHAINS)         // 2097152
#define EPSV   1e-6f
#define N1     (3*DDIM)              // 1536
#define WSCALE 256.0f
#define WINV   (1.0f/256.0f)

// GEMM tiling (mma.sync; tcgen05 blocked by compute_100 toolchain)
#define BM 128
#define BN 128
#define KC 16
#define LDT 24                       // padded smem row (fp16): 48B stride
#define TILE_ELEMS (BM*LDT)          // 3072 fp16 per array
#define ARR_BYTES  (TILE_ELEMS*2)    // 6144
#define STAGE_BYTES (3*ARR_BYTES)    // 18432: [Ah | Bh | Bl]
#define NSTAGE 4
#define SMEM_REQ (NSTAGE*STAGE_BYTES) // 73728
#define NCHUNK (DDIM/KC)             // 32

// ---------------- device scratch ----------------
__device__ __half g_xh  [MTOT*DDIM];          // x rounded to fp16
__device__ __half g_b1h [N1*DDIM];            // [n][k] (W_in|W_gate)*256 hi
__device__ __half g_b1l [N1*DDIM];            //                          lo
__device__ __half g_b2h [DDIM*DDIM];          // [n][k] W_out*256 hi
__device__ __half g_b2l [DDIM*DDIM];          //                  lo
__device__ float g_su  [MTOT*DDIM];
__device__ float g_lam [MTOT*DDIM];
__device__ float g_gate[MTOT*DDIM];
__device__ float g_h   [MTOT*DDIM];
__device__ __half g_hnh [MTOT*DDIM];          // hn rounded to fp16
__device__ float g_aggA [SEGTOT];
__device__ float g_aggBf[SEGTOT];
__device__ float g_aggBr[SEGTOT];
__device__ float g_cf   [SEGTOT];
__device__ float g_cr   [SEGTOT];

__device__ __forceinline__ float sigm(float x) { return 1.0f / (1.0f + __expf(-x)); }
__device__ __forceinline__ uint32_t pack_h2(__half a, __half b) {
    return (uint32_t)__half_as_ushort(a) | ((uint32_t)__half_as_ushort(b) << 16);
}

// ---------------- PTX helpers ----------------
__device__ __forceinline__ void mma16816(float* c, const uint32_t* a, const uint32_t* b) {
    asm volatile(
        "mma.sync.aligned.m16n8k16.row.col.f32.f16.f16.f32 "
        "{%0,%1,%2,%3}, {%4,%5,%6,%7}, {%8,%9}, {%0,%1,%2,%3};"
        : "+f"(c[0]), "+f"(c[1]), "+f"(c[2]), "+f"(c[3])
        : "r"(a[0]), "r"(a[1]), "r"(a[2]), "r"(a[3]), "r"(b[0]), "r"(b[1]));
}
__device__ __forceinline__ void ldsm4(uint32_t* r, uint32_t addr) {
    asm volatile("ldmatrix.sync.aligned.m8n8.x4.shared.b16 {%0,%1,%2,%3}, [%4];"
                 : "=r"(r[0]), "=r"(r[1]), "=r"(r[2]), "=r"(r[3]) : "r"(addr));
}
__device__ __forceinline__ void cpasync16(uint32_t saddr, const void* g) {
    asm volatile("cp.async.cg.shared.global [%0], [%1], 16;" :: "r"(saddr), "l"(g));
}
__device__ __forceinline__ void cp_commit() { asm volatile("cp.async.commit_group;"); }
template<int N> __device__ __forceinline__ void cp_wait() {
    asm volatile("cp.async.wait_group %0;" :: "n"(N));
}

// ================= conversion kernels =================
__global__ __launch_bounds__(256) void convert_x_kernel(const float* __restrict__ X)
{
    int i = blockIdx.x * 256 + threadIdx.x;            // over float4s
    float4 v = ((const float4*)X)[i];
    uint2 u;
    u.x = pack_h2(__float2half_rn(v.x), __float2half_rn(v.y));
    u.y = pack_h2(__float2half_rn(v.z), __float2half_rn(v.w));
    ((uint2*)g_xh)[i] = u;
}
__global__ __launch_bounds__(256) void convert_w1_kernel(
    const float* __restrict__ Win, const float* __restrict__ Wg)
{
    int idx = blockIdx.x * 256 + threadIdx.x;          // [0, N1*DDIM)
    int n = idx / DDIM, k = idx % DDIM;
    float w = (n < 2 * DDIM) ? Win[(size_t)k * (2 * DDIM) + n]
                             : Wg [(size_t)k * DDIM + (n - 2 * DDIM)];
    float ws = w * WSCALE;
    __half h = __float2half_rn(ws);
    g_b1h[idx] = h;
    g_b1l[idx] = __float2half_rn(ws - __half2float(h));
}
__global__ __launch_bounds__(256) void convert_w2_kernel(const float* __restrict__ Wout)
{
    int idx = blockIdx.x * 256 + threadIdx.x;          // [0, DDIM*DDIM)
    int n = idx / DDIM, k = idx % DDIM;
    float ws = Wout[(size_t)k * DDIM + n] * WSCALE;
    __half h = __float2half_rn(ws);
    g_b2h[idx] = h;
    g_b2l[idx] = __float2half_rn(ws - __half2float(h));
}

// =================================================================================
// fp16 2-term mma.sync GEMM, 4-stage cp.async pipeline.
// C = Ah(M x 512) * (Bh + Bl)(N x 512)^T, result scaled by 1/256 in epilogue.
// MODE 0: N=1536 fused [u|f|gate] epilogue.  MODE 1: N=512, +bias -> outp.
// =================================================================================
template<int MODE>
__global__ void __launch_bounds__(256) gemm_tc(
    const __half* __restrict__ Ah,
    const __half* __restrict__ Bh, const __half* __restrict__ Bl,
    const float* __restrict__ bias_a, const float* __restrict__ bias_b,
    const float* __restrict__ lbp, float* __restrict__ outp)
{
    extern __shared__ __half tiles[];                  // 4 stages x 18KB
    const uint32_t sb = (uint32_t)__cvta_generic_to_shared(tiles);
    const int tid = threadIdx.x;
    const int r0 = blockIdx.y * BM;
    const int c0 = blockIdx.x * BN;

    float acc[4][4][4];
    #pragma unroll
    for (int i = 0; i < 4; i++)
        #pragma unroll
        for (int j = 0; j < 4; j++)
            #pragma unroll
            for (int q = 0; q < 4; q++) acc[i][j][q] = 0.0f;

    const int lrow = tid >> 1;           // 0..127
    const int lseg = tid & 1;            // 16B halves of the 32B row
    const size_t gA = (size_t)(r0 + lrow) * DDIM + lseg * 8;
    const size_t gB = (size_t)(c0 + lrow) * DDIM + lseg * 8;
    const uint32_t sOff = lrow * 48 + lseg * 16;

    // prologue: chunks 0..2 -> stages 0..2
    #pragma unroll
    for (int p = 0; p < 3; p++) {
        const uint32_t st = sb + (uint32_t)p * STAGE_BYTES;
        const int k0 = p * KC;
        cpasync16(st + 0 * ARR_BYTES + sOff, Ah + gA + k0);
        cpasync16(st + 1 * ARR_BYTES + sOff, Bh + gB + k0);
        cpasync16(st + 2 * ARR_BYTES + sOff, Bl + gB + k0);
        cp_commit();
    }

    const int lane = tid & 31, wid = tid >> 5;
    const int wm = wid >> 2, wn = wid & 3;
    const int sub = lane >> 3, lr = lane & 7;
    const uint32_t boBase = (uint32_t)(wn * 32 + lr + (sub >> 1) * 8) * 48
                          + (uint32_t)(sub & 1) * 16;
    const uint32_t aoBase = (uint32_t)(wm * 64 + lr + (sub & 1) * 8) * 48
                          + (uint32_t)(sub >> 1) * 16;

    for (int c = 0; c < NCHUNK; c++) {
        cp_wait<2>();          // groups beyond chunk c still pending: c+1, c+2
        __syncthreads();       // chunk c visible; all warps done with c-1

        const uint32_t st = sb + (uint32_t)(c & 3) * STAGE_BYTES;
        const uint32_t sA  = st;
        const uint32_t sBh = st + ARR_BYTES;
        const uint32_t sBl = st + 2 * ARR_BYTES;

        uint32_t bhi[4][2], blo[4][2];
        #pragma unroll
        for (int p = 0; p < 2; p++) {
            const uint32_t bo = boBase + (uint32_t)(p * 16) * 48;
            uint32_t t4[4];
            ldsm4(t4, sBh + bo);
            bhi[2*p][0] = t4[0]; bhi[2*p][1] = t4[1]; bhi[2*p+1][0] = t4[2]; bhi[2*p+1][1] = t4[3];
            ldsm4(t4, sBl + bo);
            blo[2*p][0] = t4[0]; blo[2*p][1] = t4[1]; blo[2*p+1][0] = t4[2]; blo[2*p+1][1] = t4[3];
        }
        #pragma unroll
        for (int mi = 0; mi < 4; mi++) {
            const uint32_t ao = aoBase + (uint32_t)(mi * 16) * 48;
            uint32_t ah[4];
            ldsm4(ah, sA + ao);
            #pragma unroll
            for (int ni = 0; ni < 4; ni++) mma16816(acc[mi][ni], ah, bhi[ni]);
            #pragma unroll
            for (int ni = 0; ni < 4; ni++) mma16816(acc[mi][ni], ah, blo[ni]);
        }

        if (c + 3 < NCHUNK) {
            const uint32_t stn = sb + (uint32_t)((c + 3) & 3) * STAGE_BYTES;
            const int k0 = (c + 3) * KC;
            cpasync16(stn + 0 * ARR_BYTES + sOff, Ah + gA + k0);
            cpasync16(stn + 1 * ARR_BYTES + sOff, Bh + gB + k0);
            cpasync16(stn + 2 * ARR_BYTES + sOff, Bl + gB + k0);
        }
        cp_commit();
    }

    // -------- epilogue (descale by 1/256, then bias + activations) --------
    const int g = lane >> 2, t = lane & 3;
    float lb = 0.0f;
    if (MODE == 0) lb = lbp[0];

    #pragma unroll
    for (int mi = 0; mi < 4; mi++) {
        const int m0 = r0 + wm * 64 + mi * 16 + g;
        #pragma unroll
        for (int ni = 0; ni < 4; ni++) {
            const int nc = c0 + wn * 32 + ni * 8 + t * 2;
            float p0 = acc[mi][ni][0] * WINV, p1 = acc[mi][ni][1] * WINV;
            float p2 = acc[mi][ni][2] * WINV, p3 = acc[mi][ni][3] * WINV;
            if (MODE == 1) {
                const float b0 = bias_a[nc], b1 = bias_a[nc + 1];
                *(float2*)&outp[(size_t)m0 * DDIM + nc]       = make_float2(p0 + b0, p1 + b1);
                *(float2*)&outp[(size_t)(m0+8) * DDIM + nc]   = make_float2(p2 + b0, p3 + b1);
            } else {
                const int reg = nc >> 9;           // 0=u, 1=f, 2=gate
                const int lc = nc & 511;
                float b0, b1; float* dst;
                if (reg < 2) { b0 = bias_a[nc]; b1 = bias_a[nc + 1]; }
                else         { b0 = bias_b[lc]; b1 = bias_b[lc + 1]; }
                p0 += b0; p1 += b1; p2 += b0; p3 += b1;
                float o0, o1, o2, o3;
                if (reg == 0) {
                    o0 = p0 * sigm(p0); o1 = p1 * sigm(p1);
                    o2 = p2 * sigm(p2); o3 = p3 * sigm(p3);
                    dst = g_su;
                } else if (reg == 1) {
                    const float w = 1.0f - lb;
                    o0 = lb + w * sigm(p0); o1 = lb + w * sigm(p1);
                    o2 = lb + w * sigm(p2); o3 = lb + w * sigm(p3);
                    dst = g_lam;
                } else {
                    o0 = sigm(p0); o1 = sigm(p1); o2 = sigm(p2); o3 = sigm(p3);
                    dst = g_gate;
                }
                *(float2*)&dst[(size_t)m0 * DDIM + lc]     = make_float2(o0, o1);
                *(float2*)&dst[(size_t)(m0+8) * DDIM + lc] = make_float2(o2, o3);
            }
        }
    }
}

// ================= scan path =================
__global__ __launch_bounds__(256) void scan_phase1()
{
    int tt = blockIdx.x * blockDim.x + threadIdx.x;
    int chain = tt % CHAINS;
    int seg   = tt / CHAINS;
    int d = chain % DDIM, b = chain / DDIM;
    size_t base = ((size_t)(b * NSEQ + seg * SEGLEN)) * DDIM + d;

    float l[SEGLEN], v[SEGLEN];
    #pragma unroll
    for (int i = 0; i < SEGLEN; i++) {
        size_t idx = base + (size_t)i * DDIM;
        float li = g_lam[idx];
        float si = g_su[idx];
        l[i] = li;
        v[i] = (1.0f - li) * si;
    }
    float h = 0.0f, P = 1.0f;
    #pragma unroll
    for (int i = 0; i < SEGLEN; i++) { h = l[i] * h + v[i]; P *= l[i]; }
    float hr = 0.0f;
    #pragma unroll
    for (int i = SEGLEN - 1; i >= 0; i--) hr = l[i] * hr + v[i];

    size_t aidx = (size_t)seg * CHAINS + chain;
    g_aggA [aidx] = P;
    g_aggBf[aidx] = h;
    g_aggBr[aidx] = hr;
}
__global__ __launch_bounds__(256) void scan_phase2()
{
    int c = blockIdx.x * blockDim.x + threadIdx.x;
    float carry = 0.0f;
    #pragma unroll 8
    for (int s = 0; s < NSEG; s++) {
        size_t a = (size_t)s * CHAINS + c;
        g_cf[a] = carry;
        carry = g_aggA[a] * carry + g_aggBf[a];
    }
    carry = 0.0f;
    #pragma unroll 8
    for (int s = NSEG - 1; s >= 0; s--) {
        size_t a = (size_t)s * CHAINS + c;
        g_cr[a] = carry;
        carry = g_aggA[a] * carry + g_aggBr[a];
    }
}
__global__ __launch_bounds__(256) void scan_phase3()
{
    int tt = blockIdx.x * blockDim.x + threadIdx.x;
    int chain = tt % CHAINS;
    int seg   = tt / CHAINS;
    int d = chain % DDIM, b = chain / DDIM;
    size_t base = ((size_t)(b * NSEQ + seg * SEGLEN)) * DDIM + d;
    size_t aidx = (size_t)seg * CHAINS + chain;
    float cf = g_cf[aidx];
    float cr = g_cr[aidx];

    float l[SEGLEN], v[SEGLEN], hf[SEGLEN];
    #pragma unroll
    for (int i = 0; i < SEGLEN; i++) {
        size_t idx = base + (size_t)i * DDIM;
        float li = g_lam[idx];
        float si = g_su[idx];
        l[i] = li;
        v[i] = (1.0f - li) * si;
    }
    float h = cf;
    #pragma unroll
    for (int i = 0; i < SEGLEN; i++) { h = l[i] * h + v[i]; hf[i] = h; }
    float hr = cr;
    #pragma unroll
    for (int i = SEGLEN - 1; i >= 0; i--) {
        hr = l[i] * hr + v[i];
        g_h[base + (size_t)i * DDIM] = hf[i] + hr;
    }
}
__global__ __launch_bounds__(256) void rms_gate_kernel()
{
    int warp = threadIdx.x >> 5, lane = threadIdx.x & 31;
    int row = blockIdx.x * 8 + warp;
    size_t base = (size_t)row * DDIM + lane * 4;

    float4 hv[4];
    float ss = 0.0f;
    #pragma unroll
    for (int j = 0; j < 4; j++) {
        hv[j] = *(const float4*)&g_h[base + j * 128];
        ss += hv[j].x * hv[j].x + hv[j].y * hv[j].y + hv[j].z * hv[j].z + hv[j].w * hv[j].w;
    }
    #pragma unroll
    for (int o = 16; o > 0; o >>= 1) ss += __shfl_xor_sync(0xffffffff, ss, o);
    float scale = rsqrtf(ss * (1.0f / DDIM) + EPSV);

    #pragma unroll
    for (int j = 0; j < 4; j++) {
        float4 gv = *(const float4*)&g_gate[base + j * 128];
        float o0 = hv[j].x * scale * gv.x;
        float o1 = hv[j].y * scale * gv.y;
        float o2 = hv[j].z * scale * gv.z;
        float o3 = hv[j].w * scale * gv.w;
        uint2 u;
        u.x = pack_h2(__float2half_rn(o0), __float2half_rn(o1));
        u.y = pack_h2(__float2half_rn(o2), __float2half_rn(o3));
        *(uint2*)&g_hnh[base + j * 128] = u;
    }
}

// ================= launch =================
extern "C" void kernel_launch(void* const* d_in, const int* in_sizes, int n_in,
                              void* d_out, int out_size)
{
    const float* x    = (const float*)d_in[0];
    const float* lb   = (const float*)d_in[1];
    const float* Win  = (const float*)d_in[2];
    const float* bin  = (const float*)d_in[3];
    const float* Wg   = (const float*)d_in[4];
    const float* bg   = (const float*)d_in[5];
    const float* Wout = (const float*)d_in[6];
    const float* bout = (const float*)d_in[7];
    float* out = (float*)d_out;

    __half *xh, *b1h, *b1l, *b2h, *b2l, *hnh;
    cudaGetSymbolAddress((void**)&xh,  g_xh);
    cudaGetSymbolAddress((void**)&b1h, g_b1h);
    cudaGetSymbolAddress((void**)&b1l, g_b1l);
    cudaGetSymbolAddress((void**)&b2h, g_b2h);
    cudaGetSymbolAddress((void**)&b2l, g_b2l);
    cudaGetSymbolAddress((void**)&hnh, g_hnh);

    cudaFuncSetAttribute(gemm_tc<0>, cudaFuncAttributeMaxDynamicSharedMemorySize, SMEM_REQ);
    cudaFuncSetAttribute(gemm_tc<1>, cudaFuncAttributeMaxDynamicSharedMemorySize, SMEM_REQ);

    convert_x_kernel<<<(MTOT * DDIM / 4) / 256, 256>>>(x);
    convert_w1_kernel<<<(N1 * DDIM) / 256, 256>>>(Win, Wg);
    convert_w2_kernel<<<(DDIM * DDIM) / 256, 256>>>(Wout);

    dim3 g1(N1 / BN, MTOT / BM);           // (12, 512)
    gemm_tc<0><<<g1, 256, SMEM_REQ>>>(xh, b1h, b1l, bin, bg, lb, nullptr);

    scan_phase1<<<SEGTOT / 256, 256>>>();
    scan_phase2<<<CHAINS / 256, 256>>>();
    scan_phase3<<<SEGTOT / 256, 256>>>();
    rms_gate_kernel<<<MTOT / 8, 256>>>();

    dim3 g2(DDIM / BN, MTOT / BM);         // (4, 512)
    gemm_tc<1><<<g2, 256, SMEM_REQ>>>(hnh, b2h, b2l, bout, nullptr, nullptr, out);
}

// round 12
// speedup vs baseline: 1.6618x; 1.1671x over previous
#include <cuda_runtime.h>
#include <cuda_fp16.h>
#include <stdint.h>
#include <math.h>

// Problem dims (fixed by the reference)
#define BATCH  16
#define NSEQ   4096
#define DDIM   512
#define MTOT   (BATCH*NSEQ)          // 65536 rows
#define CHAINS (BATCH*DDIM)          // 8192 scan chains
#define SEGLEN 16
#define NSEG   (NSEQ/SEGLEN)         // 256
#define SEGTOT (NSEG*CHAINS)         // 2097152
#define EPSV   1e-6f
#define N1     (3*DDIM)              // 1536
#define WSCALE 256.0f
#define WINV   (1.0f/256.0f)

// GEMM tiling (mma.sync; tcgen05 blocked by compute_100 toolchain)
#define BM 128
#define BN 128
#define KC 16
#define LDT 24                       // padded smem row (fp16): 48B stride
#define TILE_ELEMS (BM*LDT)          // 3072 fp16 per array
#define ARR_BYTES  (TILE_ELEMS*2)    // 6144
#define STAGE_BYTES (2*ARR_BYTES)    // 12288: [Ah | Bh]
#define NSTAGE 4
#define SMEM_REQ (NSTAGE*STAGE_BYTES) // 49152
#define NCHUNK (DDIM/KC)             // 32

// ---------------- device scratch ----------------
__device__ __half g_xh  [MTOT*DDIM];          // x rounded to fp16
__device__ __half g_b1h [N1*DDIM];            // [n][k] (W_in|W_gate)*256 fp16
__device__ __half g_b2h [DDIM*DDIM];          // [n][k] W_out*256 fp16
__device__ float g_su  [MTOT*DDIM];
__device__ float g_lam [MTOT*DDIM];
__device__ float g_gate[MTOT*DDIM];
__device__ float g_h   [MTOT*DDIM];
__device__ __half g_hnh [MTOT*DDIM];          // hn rounded to fp16
__device__ float g_aggA [SEGTOT];
__device__ float g_aggBf[SEGTOT];
__device__ float g_aggBr[SEGTOT];
__device__ float g_cf   [SEGTOT];
__device__ float g_cr   [SEGTOT];

__device__ __forceinline__ float sigm(float x) { return 1.0f / (1.0f + __expf(-x)); }
__device__ __forceinline__ uint32_t pack_h2(__half a, __half b) {
    return (uint32_t)__half_as_ushort(a) | ((uint32_t)__half_as_ushort(b) << 16);
}

// ---------------- PTX helpers ----------------
__device__ __forceinline__ void mma16816(float* c, const uint32_t* a, const uint32_t* b) {
    asm volatile(
        "mma.sync.aligned.m16n8k16.row.col.f32.f16.f16.f32 "
        "{%0,%1,%2,%3}, {%4,%5,%6,%7}, {%8,%9}, {%0,%1,%2,%3};"
        : "+f"(c[0]), "+f"(c[1]), "+f"(c[2]), "+f"(c[3])
        : "r"(a[0]), "r"(a[1]), "r"(a[2]), "r"(a[3]), "r"(b[0]), "r"(b[1]));
}
__device__ __forceinline__ void ldsm4(uint32_t* r, uint32_t addr) {
    asm volatile("ldmatrix.sync.aligned.m8n8.x4.shared.b16 {%0,%1,%2,%3}, [%4];"
                 : "=r"(r[0]), "=r"(r[1]), "=r"(r[2]), "=r"(r[3]) : "r"(addr));
}
__device__ __forceinline__ void cpasync16(uint32_t saddr, const void* g) {
    asm volatile("cp.async.cg.shared.global [%0], [%1], 16;" :: "r"(saddr), "l"(g));
}
__device__ __forceinline__ void cp_commit() { asm volatile("cp.async.commit_group;"); }
template<int N> __device__ __forceinline__ void cp_wait() {
    asm volatile("cp.async.wait_group %0;" :: "n"(N));
}

// ================= conversion kernels =================
__global__ __launch_bounds__(256) void convert_x_kernel(const float* __restrict__ X)
{
    int i = blockIdx.x * 256 + threadIdx.x;            // over float4s
    float4 v = ((const float4*)X)[i];
    uint2 u;
    u.x = pack_h2(__float2half_rn(v.x), __float2half_rn(v.y));
    u.y = pack_h2(__float2half_rn(v.z), __float2half_rn(v.w));
    ((uint2*)g_xh)[i] = u;
}
__global__ __launch_bounds__(256) void convert_w1_kernel(
    const float* __restrict__ Win, const float* __restrict__ Wg)
{
    int idx = blockIdx.x * 256 + threadIdx.x;          // [0, N1*DDIM)
    int n = idx / DDIM, k = idx % DDIM;
    float w = (n < 2 * DDIM) ? Win[(size_t)k * (2 * DDIM) + n]
                             : Wg [(size_t)k * DDIM + (n - 2 * DDIM)];
    g_b1h[idx] = __float2half_rn(w * WSCALE);
}
__global__ __launch_bounds__(256) void convert_w2_kernel(const float* __restrict__ Wout)
{
    int idx = blockIdx.x * 256 + threadIdx.x;          // [0, DDIM*DDIM)
    int n = idx / DDIM, k = idx % DDIM;
    g_b2h[idx] = __float2half_rn(Wout[(size_t)k * DDIM + n] * WSCALE);
}

// =================================================================================
// fp16 mma.sync GEMM, 4-stage cp.async pipeline, 16 mmas + 6 ldsm per chunk.
// C = Ah(M x 512) * Bh(N x 512)^T, result scaled by 1/256 in epilogue.
// MODE 0: N=1536 fused [u|f|gate] epilogue.  MODE 1: N=512, +bias -> outp.
// =================================================================================
template<int MODE>
__global__ void __launch_bounds__(256) gemm_tc(
    const __half* __restrict__ Ah, const __half* __restrict__ Bh,
    const float* __restrict__ bias_a, const float* __restrict__ bias_b,
    const float* __restrict__ lbp, float* __restrict__ outp)
{
    extern __shared__ __half tiles[];                  // 4 stages x 12KB
    const uint32_t sb = (uint32_t)__cvta_generic_to_shared(tiles);
    const int tid = threadIdx.x;
    const int r0 = blockIdx.y * BM;
    const int c0 = blockIdx.x * BN;

    float acc[4][4][4];
    #pragma unroll
    for (int i = 0; i < 4; i++)
        #pragma unroll
        for (int j = 0; j < 4; j++)
            #pragma unroll
            for (int q = 0; q < 4; q++) acc[i][j][q] = 0.0f;

    const int lrow = tid >> 1;           // 0..127
    const int lseg = tid & 1;            // 16B halves of the 32B row
    const size_t gA = (size_t)(r0 + lrow) * DDIM + lseg * 8;
    const size_t gB = (size_t)(c0 + lrow) * DDIM + lseg * 8;
    const uint32_t sOff = lrow * 48 + lseg * 16;

    // prologue: chunks 0..2 -> stages 0..2
    #pragma unroll
    for (int p = 0; p < 3; p++) {
        const uint32_t st = sb + (uint32_t)p * STAGE_BYTES;
        const int k0 = p * KC;
        cpasync16(st + sOff,             Ah + gA + k0);
        cpasync16(st + ARR_BYTES + sOff, Bh + gB + k0);
        cp_commit();
    }

    const int lane = tid & 31, wid = tid >> 5;
    const int wm = wid >> 2, wn = wid & 3;
    const int sub = lane >> 3, lr = lane & 7;
    const uint32_t boBase = (uint32_t)(wn * 32 + lr + (sub >> 1) * 8) * 48
                          + (uint32_t)(sub & 1) * 16;
    const uint32_t aoBase = (uint32_t)(wm * 64 + lr + (sub & 1) * 8) * 48
                          + (uint32_t)(sub >> 1) * 16;

    for (int c = 0; c < NCHUNK; c++) {
        cp_wait<2>();          // groups beyond chunk c still pending: c+1, c+2
        __syncthreads();       // chunk c visible; all warps done with c-1

        const uint32_t st = sb + (uint32_t)(c & 3) * STAGE_BYTES;
        const uint32_t sA  = st;
        const uint32_t sBh = st + ARR_BYTES;

        uint32_t bhi[4][2];
        #pragma unroll
        for (int p = 0; p < 2; p++) {
            const uint32_t bo = boBase + (uint32_t)(p * 16) * 48;
            uint32_t t4[4];
            ldsm4(t4, sBh + bo);
            bhi[2*p][0] = t4[0]; bhi[2*p][1] = t4[1]; bhi[2*p+1][0] = t4[2]; bhi[2*p+1][1] = t4[3];
        }
        #pragma unroll
        for (int mi = 0; mi < 4; mi++) {
            const uint32_t ao = aoBase + (uint32_t)(mi * 16) * 48;
            uint32_t ah[4];
            ldsm4(ah, sA + ao);
            #pragma unroll
            for (int ni = 0; ni < 4; ni++) mma16816(acc[mi][ni], ah, bhi[ni]);
        }

        if (c + 3 < NCHUNK) {
            const uint32_t stn = sb + (uint32_t)((c + 3) & 3) * STAGE_BYTES;
            const int k0 = (c + 3) * KC;
            cpasync16(stn + sOff,             Ah + gA + k0);
            cpasync16(stn + ARR_BYTES + sOff, Bh + gB + k0);
        }
        cp_commit();
    }

    // -------- epilogue (descale by 1/256, then bias + activations) --------
    const int g = lane >> 2, t = lane & 3;
    float lb = 0.0f;
    if (MODE == 0) lb = lbp[0];

    #pragma unroll
    for (int mi = 0; mi < 4; mi++) {
        const int m0 = r0 + wm * 64 + mi * 16 + g;
        #pragma unroll
        for (int ni = 0; ni < 4; ni++) {
            const int nc = c0 + wn * 32 + ni * 8 + t * 2;
            float p0 = acc[mi][ni][0] * WINV, p1 = acc[mi][ni][1] * WINV;
            float p2 = acc[mi][ni][2] * WINV, p3 = acc[mi][ni][3] * WINV;
            if (MODE == 1) {
                const float b0 = bias_a[nc], b1 = bias_a[nc + 1];
                *(float2*)&outp[(size_t)m0 * DDIM + nc]       = make_float2(p0 + b0, p1 + b1);
                *(float2*)&outp[(size_t)(m0+8) * DDIM + nc]   = make_float2(p2 + b0, p3 + b1);
            } else {
                const int reg = nc >> 9;           // 0=u, 1=f, 2=gate
                const int lc = nc & 511;
                float b0, b1; float* dst;
                if (reg < 2) { b0 = bias_a[nc]; b1 = bias_a[nc + 1]; }
                else         { b0 = bias_b[lc]; b1 = bias_b[lc + 1]; }
                p0 += b0; p1 += b1; p2 += b0; p3 += b1;
                float o0, o1, o2, o3;
                if (reg == 0) {
                    o0 = p0 * sigm(p0); o1 = p1 * sigm(p1);
                    o2 = p2 * sigm(p2); o3 = p3 * sigm(p3);
                    dst = g_su;
                } else if (reg == 1) {
                    const float w = 1.0f - lb;
                    o0 = lb + w * sigm(p0); o1 = lb + w * sigm(p1);
                    o2 = lb + w * sigm(p2); o3 = lb + w * sigm(p3);
                    dst = g_lam;
                } else {
                    o0 = sigm(p0); o1 = sigm(p1); o2 = sigm(p2); o3 = sigm(p3);
                    dst = g_gate;
                }
                *(float2*)&dst[(size_t)m0 * DDIM + lc]     = make_float2(o0, o1);
                *(float2*)&dst[(size_t)(m0+8) * DDIM + lc] = make_float2(o2, o3);
            }
        }
    }
}

// ================= scan path =================
__global__ __launch_bounds__(256) void scan_phase1()
{
    int tt = blockIdx.x * blockDim.x + threadIdx.x;
    int chain = tt % CHAINS;
    int seg   = tt / CHAINS;
    int d = chain % DDIM, b = chain / DDIM;
    size_t base = ((size_t)(b * NSEQ + seg * SEGLEN)) * DDIM + d;

    float l[SEGLEN], v[SEGLEN];
    #pragma unroll
    for (int i = 0; i < SEGLEN; i++) {
        size_t idx = base + (size_t)i * DDIM;
        float li = g_lam[idx];
        float si = g_su[idx];
        l[i] = li;
        v[i] = (1.0f - li) * si;
    }
    float h = 0.0f, P = 1.0f;
    #pragma unroll
    for (int i = 0; i < SEGLEN; i++) { h = l[i] * h + v[i]; P *= l[i]; }
    float hr = 0.0f;
    #pragma unroll
    for (int i = SEGLEN - 1; i >= 0; i--) hr = l[i] * hr + v[i];

    size_t aidx = (size_t)seg * CHAINS + chain;
    g_aggA [aidx] = P;
    g_aggBf[aidx] = h;
    g_aggBr[aidx] = hr;
}
__global__ __launch_bounds__(256) void scan_phase2()
{
    int c = blockIdx.x * blockDim.x + threadIdx.x;
    float carry = 0.0f;
    #pragma unroll 8
    for (int s = 0; s < NSEG; s++) {
        size_t a = (size_t)s * CHAINS + c;
        g_cf[a] = carry;
        carry = g_aggA[a] * carry + g_aggBf[a];
    }
    carry = 0.0f;
    #pragma unroll 8
    for (int s = NSEG - 1; s >= 0; s--) {
        size_t a = (size_t)s * CHAINS + c;
        g_cr[a] = carry;
        carry = g_aggA[a] * carry + g_aggBr[a];
    }
}
__global__ __launch_bounds__(256) void scan_phase3()
{
    int tt = blockIdx.x * blockDim.x + threadIdx.x;
    int chain = tt % CHAINS;
    int seg   = tt / CHAINS;
    int d = chain % DDIM, b = chain / DDIM;
    size_t base = ((size_t)(b * NSEQ + seg * SEGLEN)) * DDIM + d;
    size_t aidx = (size_t)seg * CHAINS + chain;
    float cf = g_cf[aidx];
    float cr = g_cr[aidx];

    float l[SEGLEN], v[SEGLEN], hf[SEGLEN];
    #pragma unroll
    for (int i = 0; i < SEGLEN; i++) {
        size_t idx = base + (size_t)i * DDIM;
        float li = g_lam[idx];
        float si = g_su[idx];
        l[i] = li;
        v[i] = (1.0f - li) * si;
    }
    float h = cf;
    #pragma unroll
    for (int i = 0; i < SEGLEN; i++) { h = l[i] * h + v[i]; hf[i] = h; }
    float hr = cr;
    #pragma unroll
    for (int i = SEGLEN - 1; i >= 0; i--) {
        hr = l[i] * hr + v[i];
        g_h[base + (size_t)i * DDIM] = hf[i] + hr;
    }
}
__global__ __launch_bounds__(256) void rms_gate_kernel()
{
    int warp = threadIdx.x >> 5, lane = threadIdx.x & 31;
    int row = blockIdx.x * 8 + warp;
    size_t base = (size_t)row * DDIM + lane * 4;

    float4 hv[4];
    float ss = 0.0f;
    #pragma unroll
    for (int j = 0; j < 4; j++) {
        hv[j] = *(const float4*)&g_h[base + j * 128];
        ss += hv[j].x * hv[j].x + hv[j].y * hv[j].y + hv[j].z * hv[j].z + hv[j].w * hv[j].w;
    }
    #pragma unroll
    for (int o = 16; o > 0; o >>= 1) ss += __shfl_xor_sync(0xffffffff, ss, o);
    float scale = rsqrtf(ss * (1.0f / DDIM) + EPSV);

    #pragma unroll
    for (int j = 0; j < 4; j++) {
        float4 gv = *(const float4*)&g_gate[base + j * 128];
        float o0 = hv[j].x * scale * gv.x;
        float o1 = hv[j].y * scale * gv.y;
        float o2 = hv[j].z * scale * gv.z;
        float o3 = hv[j].w * scale * gv.w;
        uint2 u;
        u.x = pack_h2(__float2half_rn(o0), __float2half_rn(o1));
        u.y = pack_h2(__float2half_rn(o2), __float2half_rn(o3));
        *(uint2*)&g_hnh[base + j * 128] = u;
    }
}

// ================= launch =================
extern "C" void kernel_launch(void* const* d_in, const int* in_sizes, int n_in,
                              void* d_out, int out_size)
{
    const float* x    = (const float*)d_in[0];
    const float* lb   = (const float*)d_in[1];
    const float* Win  = (const float*)d_in[2];
    const float* bin  = (const float*)d_in[3];
    const float* Wg   = (const float*)d_in[4];
    const float* bg   = (const float*)d_in[5];
    const float* Wout = (const float*)d_in[6];
    const float* bout = (const float*)d_in[7];
    float* out = (float*)d_out;

    __half *xh, *b1h, *b2h, *hnh;
    cudaGetSymbolAddress((void**)&xh,  g_xh);
    cudaGetSymbolAddress((void**)&b1h, g_b1h);
    cudaGetSymbolAddress((void**)&b2h, g_b2h);
    cudaGetSymbolAddress((void**)&hnh, g_hnh);

    cudaFuncSetAttribute(gemm_tc<0>, cudaFuncAttributeMaxDynamicSharedMemorySize, SMEM_REQ);
    cudaFuncSetAttribute(gemm_tc<1>, cudaFuncAttributeMaxDynamicSharedMemorySize, SMEM_REQ);

    convert_x_kernel<<<(MTOT * DDIM / 4) / 256, 256>>>(x);
    convert_w1_kernel<<<(N1 * DDIM) / 256, 256>>>(Win, Wg);
    convert_w2_kernel<<<(DDIM * DDIM) / 256, 256>>>(Wout);

    dim3 g1(N1 / BN, MTOT / BM);           // (12, 512)
    gemm_tc<0><<<g1, 256, SMEM_REQ>>>(xh, b1h, bin, bg, lb, nullptr);

    scan_phase1<<<SEGTOT / 256, 256>>>();
    scan_phase2<<<CHAINS / 256, 256>>>();
    scan_phase3<<<SEGTOT / 256, 256>>>();
    rms_gate_kernel<<<MTOT / 8, 256>>>();

    dim3 g2(DDIM / BN, MTOT / BM);         // (4, 512)
    gemm_tc<1><<<g2, 256, SMEM_REQ>>>(hnh, b2h, bout, nullptr, nullptr, out);
}

// round 13
// speedup vs baseline: 1.6959x; 1.0205x over previous
#include <cuda_runtime.h>
#include <cuda_fp16.h>
#include <stdint.h>
#include <math.h>

// Problem dims (fixed by the reference)
#define BATCH  16
#define NSEQ   4096
#define DDIM   512
#define MTOT   (BATCH*NSEQ)          // 65536 rows
#define CHAINS (BATCH*DDIM)          // 8192 scan chains
#define SEGLEN 16
#define NSEG   (NSEQ/SEGLEN)         // 256
#define SEGTOT (NSEG*CHAINS)         // 2097152
#define EPSV   1e-6f
#define N1     (3*DDIM)              // 1536
#define WSCALE 256.0f
#define WINV   (1.0f/256.0f)

// GEMM tiling (mma.sync; tcgen05 blocked by compute_100 toolchain)
#define BM 128
#define BN 128
#define KC 16
#define LDT 24                       // padded smem row (fp16): 48B stride
#define TILE_ELEMS (BM*LDT)          // 3072 fp16 per array
#define ARR_BYTES  (TILE_ELEMS*2)    // 6144
#define STAGE_BYTES (2*ARR_BYTES)    // 12288: [Ah | Bh]
#define NSTAGE 4
#define SMEM_REQ (NSTAGE*STAGE_BYTES) // 49152
#define NCHUNK (DDIM/KC)             // 32

// ---------------- device scratch ----------------
__device__ __half g_xh  [MTOT*DDIM];          // x rounded to fp16
__device__ __half g_b1h [N1*DDIM];            // [n][k] (W_in|W_gate)*256 fp16
__device__ __half g_b2h [DDIM*DDIM];          // [n][k] W_out*256 fp16
__device__ float g_su  [MTOT*DDIM];
__device__ float g_lam [MTOT*DDIM];
__device__ float g_gate[MTOT*DDIM];
__device__ __half g_hnh [MTOT*DDIM];          // hn rounded to fp16
__device__ float g_aggA [SEGTOT];
__device__ float g_aggBf[SEGTOT];
__device__ float g_aggBr[SEGTOT];
__device__ float g_cf   [SEGTOT];
__device__ float g_cr   [SEGTOT];

__device__ __forceinline__ float sigm(float x) { return 1.0f / (1.0f + __expf(-x)); }
__device__ __forceinline__ uint32_t pack_h2(__half a, __half b) {
    return (uint32_t)__half_as_ushort(a) | ((uint32_t)__half_as_ushort(b) << 16);
}

// ---------------- PTX helpers ----------------
__device__ __forceinline__ void mma16816(float* c, const uint32_t* a, const uint32_t* b) {
    asm volatile(
        "mma.sync.aligned.m16n8k16.row.col.f32.f16.f16.f32 "
        "{%0,%1,%2,%3}, {%4,%5,%6,%7}, {%8,%9}, {%0,%1,%2,%3};"
        : "+f"(c[0]), "+f"(c[1]), "+f"(c[2]), "+f"(c[3])
        : "r"(a[0]), "r"(a[1]), "r"(a[2]), "r"(a[3]), "r"(b[0]), "r"(b[1]));
}
__device__ __forceinline__ void ldsm4(uint32_t* r, uint32_t addr) {
    asm volatile("ldmatrix.sync.aligned.m8n8.x4.shared.b16 {%0,%1,%2,%3}, [%4];"
                 : "=r"(r[0]), "=r"(r[1]), "=r"(r[2]), "=r"(r[3]) : "r"(addr));
}
__device__ __forceinline__ void cpasync16(uint32_t saddr, const void* g) {
    asm volatile("cp.async.cg.shared.global [%0], [%1], 16;" :: "r"(saddr), "l"(g));
}
__device__ __forceinline__ void cp_commit() { asm volatile("cp.async.commit_group;"); }
template<int N> __device__ __forceinline__ void cp_wait() {
    asm volatile("cp.async.wait_group %0;" :: "n"(N));
}

// ================= conversion kernels =================
__global__ __launch_bounds__(256) void convert_x_kernel(const float* __restrict__ X)
{
    int i = blockIdx.x * 256 + threadIdx.x;            // over float4s
    float4 v = ((const float4*)X)[i];
    uint2 u;
    u.x = pack_h2(__float2half_rn(v.x), __float2half_rn(v.y));
    u.y = pack_h2(__float2half_rn(v.z), __float2half_rn(v.w));
    ((uint2*)g_xh)[i] = u;
}
__global__ __launch_bounds__(256) void convert_w1_kernel(
    const float* __restrict__ Win, const float* __restrict__ Wg)
{
    int idx = blockIdx.x * 256 + threadIdx.x;          // [0, N1*DDIM)
    int n = idx / DDIM, k = idx % DDIM;
    float w = (n < 2 * DDIM) ? Win[(size_t)k * (2 * DDIM) + n]
                             : Wg [(size_t)k * DDIM + (n - 2 * DDIM)];
    g_b1h[idx] = __float2half_rn(w * WSCALE);
}
__global__ __launch_bounds__(256) void convert_w2_kernel(const float* __restrict__ Wout)
{
    int idx = blockIdx.x * 256 + threadIdx.x;          // [0, DDIM*DDIM)
    int n = idx / DDIM, k = idx % DDIM;
    g_b2h[idx] = __float2half_rn(Wout[(size_t)k * DDIM + n] * WSCALE);
}

// =================================================================================
// fp16 mma.sync GEMM, 4-stage cp.async pipeline + REGISTER fragment pipelining:
// each iteration ldsm's chunk c+1's fragments BEFORE running chunk c's mmas, so
// the smem-load latency hides behind the mma stream (fixes the latency-bound
// profile: tensor 34%, no pipe >43%).
// =================================================================================
template<int MODE>
__global__ void __launch_bounds__(256, 2) gemm_tc(
    const __half* __restrict__ Ah, const __half* __restrict__ Bh,
    const float* __restrict__ bias_a, const float* __restrict__ bias_b,
    const float* __restrict__ lbp, float* __restrict__ outp)
{
    extern __shared__ __half tiles[];                  // 4 stages x 12KB
    const uint32_t sb = (uint32_t)__cvta_generic_to_shared(tiles);
    const int tid = threadIdx.x;
    const int r0 = blockIdx.y * BM;
    const int c0 = blockIdx.x * BN;

    float acc[4][4][4];
    #pragma unroll
    for (int i = 0; i < 4; i++)
        #pragma unroll
        for (int j = 0; j < 4; j++)
            #pragma unroll
            for (int q = 0; q < 4; q++) acc[i][j][q] = 0.0f;

    const int lrow = tid >> 1;
    const int lseg = tid & 1;
    const size_t gA = (size_t)(r0 + lrow) * DDIM + lseg * 8;
    const size_t gB = (size_t)(c0 + lrow) * DDIM + lseg * 8;
    const uint32_t sOff = lrow * 48 + lseg * 16;

    // prologue: chunks 0..2 -> stages 0..2
    #pragma unroll
    for (int p = 0; p < 3; p++) {
        const uint32_t st = sb + (uint32_t)p * STAGE_BYTES;
        const int k0 = p * KC;
        cpasync16(st + sOff,             Ah + gA + k0);
        cpasync16(st + ARR_BYTES + sOff, Bh + gB + k0);
        cp_commit();
    }

    const int lane = tid & 31, wid = tid >> 5;
    const int wm = wid >> 2, wn = wid & 3;
    const int sub = lane >> 3, lr = lane & 7;
    const uint32_t boBase = (uint32_t)(wn * 32 + lr + (sub >> 1) * 8) * 48
                          + (uint32_t)(sub & 1) * 16;
    const uint32_t aoBase = (uint32_t)(wm * 64 + lr + (sub & 1) * 8) * 48
                          + (uint32_t)(sub >> 1) * 16;

    uint32_t aF[2][4][4], bF[2][4][2];

    // frags for chunk 0 (stage 0 ready after wait<1>: chunks 0,1 landed)
    cp_wait<1>();
    __syncthreads();
    {
        const uint32_t st = sb;
        #pragma unroll
        for (int p = 0; p < 2; p++) {
            uint32_t t4[4];
            ldsm4(t4, st + ARR_BYTES + boBase + (uint32_t)(p * 16) * 48);
            bF[0][2*p][0] = t4[0]; bF[0][2*p][1] = t4[1];
            bF[0][2*p+1][0] = t4[2]; bF[0][2*p+1][1] = t4[3];
        }
        #pragma unroll
        for (int mi = 0; mi < 4; mi++)
            ldsm4(aF[0][mi], st + aoBase + (uint32_t)(mi * 16) * 48);
    }

    for (int c = 0; c < NCHUNK; c++) {
        const int cur = c & 1, nxt = cur ^ 1;
        if (c > 0) {
            cp_wait<1>();      // chunks <= c+1 landed
            __syncthreads();   // all warps past iter c-1 (stage reuse safe)
        }
        // prefetch frags for chunk c+1 (stage (c+1)&3)
        if (c + 1 < NCHUNK) {
            const uint32_t st = sb + (uint32_t)((c + 1) & 3) * STAGE_BYTES;
            #pragma unroll
            for (int p = 0; p < 2; p++) {
                uint32_t t4[4];
                ldsm4(t4, st + ARR_BYTES + boBase + (uint32_t)(p * 16) * 48);
                bF[nxt][2*p][0] = t4[0]; bF[nxt][2*p][1] = t4[1];
                bF[nxt][2*p+1][0] = t4[2]; bF[nxt][2*p+1][1] = t4[3];
            }
            #pragma unroll
            for (int mi = 0; mi < 4; mi++)
                ldsm4(aF[nxt][mi], st + aoBase + (uint32_t)(mi * 16) * 48);
        }
        // issue loads for chunk c+3 into stage (c+3)&3
        if (c + 3 < NCHUNK) {
            const uint32_t stn = sb + (uint32_t)((c + 3) & 3) * STAGE_BYTES;
            const int k0 = (c + 3) * KC;
            cpasync16(stn + sOff,             Ah + gA + k0);
            cpasync16(stn + ARR_BYTES + sOff, Bh + gB + k0);
        }
        cp_commit();
        // mmas for chunk c (fragments loaded last iteration — no ldsm dependency)
        #pragma unroll
        for (int mi = 0; mi < 4; mi++)
            #pragma unroll
            for (int ni = 0; ni < 4; ni++)
                mma16816(acc[mi][ni], aF[cur][mi], bF[cur][ni]);
    }

    // -------- epilogue (descale by 1/256, then bias + activations) --------
    const int g = lane >> 2, t = lane & 3;
    float lb = 0.0f;
    if (MODE == 0) lb = lbp[0];

    #pragma unroll
    for (int mi = 0; mi < 4; mi++) {
        const int m0 = r0 + wm * 64 + mi * 16 + g;
        #pragma unroll
        for (int ni = 0; ni < 4; ni++) {
            const int nc = c0 + wn * 32 + ni * 8 + t * 2;
            float p0 = acc[mi][ni][0] * WINV, p1 = acc[mi][ni][1] * WINV;
            float p2 = acc[mi][ni][2] * WINV, p3 = acc[mi][ni][3] * WINV;
            if (MODE == 1) {
                const float b0 = bias_a[nc], b1 = bias_a[nc + 1];
                *(float2*)&outp[(size_t)m0 * DDIM + nc]       = make_float2(p0 + b0, p1 + b1);
                *(float2*)&outp[(size_t)(m0+8) * DDIM + nc]   = make_float2(p2 + b0, p3 + b1);
            } else {
                const int reg = nc >> 9;           // 0=u, 1=f, 2=gate
                const int lc = nc & 511;
                float b0, b1; float* dst;
                if (reg < 2) { b0 = bias_a[nc]; b1 = bias_a[nc + 1]; }
                else         { b0 = bias_b[lc]; b1 = bias_b[lc + 1]; }
                p0 += b0; p1 += b1; p2 += b0; p3 += b1;
                float o0, o1, o2, o3;
                if (reg == 0) {
                    o0 = p0 * sigm(p0); o1 = p1 * sigm(p1);
                    o2 = p2 * sigm(p2); o3 = p3 * sigm(p3);
                    dst = g_su;
                } else if (reg == 1) {
                    const float w = 1.0f - lb;
                    o0 = lb + w * sigm(p0); o1 = lb + w * sigm(p1);
                    o2 = lb + w * sigm(p2); o3 = lb + w * sigm(p3);
                    dst = g_lam;
                } else {
                    o0 = sigm(p0); o1 = sigm(p1); o2 = sigm(p2); o3 = sigm(p3);
                    dst = g_gate;
                }
                *(float2*)&dst[(size_t)m0 * DDIM + lc]     = make_float2(o0, o1);
                *(float2*)&dst[(size_t)(m0+8) * DDIM + lc] = make_float2(o2, o3);
            }
        }
    }
}

// ================= scan path =================
__global__ __launch_bounds__(256) void scan_phase1()
{
    int tt = blockIdx.x * blockDim.x + threadIdx.x;
    int chain = tt % CHAINS;
    int seg   = tt / CHAINS;
    int d = chain % DDIM, b = chain / DDIM;
    size_t base = ((size_t)(b * NSEQ + seg * SEGLEN)) * DDIM + d;

    float l[SEGLEN], v[SEGLEN];
    #pragma unroll
    for (int i = 0; i < SEGLEN; i++) {
        size_t idx = base + (size_t)i * DDIM;
        float li = g_lam[idx];
        float si = g_su[idx];
        l[i] = li;
        v[i] = (1.0f - li) * si;
    }
    float h = 0.0f, P = 1.0f;
    #pragma unroll
    for (int i = 0; i < SEGLEN; i++) { h = l[i] * h + v[i]; P *= l[i]; }
    float hr = 0.0f;
    #pragma unroll
    for (int i = SEGLEN - 1; i >= 0; i--) hr = l[i] * hr + v[i];

    size_t aidx = (size_t)seg * CHAINS + chain;
    g_aggA [aidx] = P;
    g_aggBf[aidx] = h;
    g_aggBr[aidx] = hr;
}
__global__ __launch_bounds__(256) void scan_phase2()
{
    int c = blockIdx.x * blockDim.x + threadIdx.x;
    float carry = 0.0f;
    #pragma unroll 8
    for (int s = 0; s < NSEG; s++) {
        size_t a = (size_t)s * CHAINS + c;
        g_cf[a] = carry;
        carry = g_aggA[a] * carry + g_aggBf[a];
    }
    carry = 0.0f;
    #pragma unroll 8
    for (int s = NSEG - 1; s >= 0; s--) {
        size_t a = (size_t)s * CHAINS + c;
        g_cr[a] = carry;
        carry = g_aggA[a] * carry + g_aggBr[a];
    }
}
// =================================================================================
// Fused scan_phase3 + SimpleRMSNorm + gate: block = one (batch, segment) of 16
// rows x 512 d. h never touches HBM (32KB smem tile), output written as fp16.
// =================================================================================
__global__ __launch_bounds__(512) void scan3_rms_kernel()
{
    __shared__ float h_tile[SEGLEN][DDIM];     // 32 KB
    __shared__ float scale_sm[SEGLEN];
    const int blk = blockIdx.x;                // b*NSEG + seg
    const int b = blk / NSEG, seg = blk % NSEG;
    const int d = threadIdx.x;
    const int chain = b * DDIM + d;
    const size_t aidx = (size_t)seg * CHAINS + chain;
    const float cf = g_cf[aidx];
    const float cr = g_cr[aidx];
    const size_t base = ((size_t)(b * NSEQ + seg * SEGLEN)) * DDIM + d;

    float l[SEGLEN], v[SEGLEN];
    #pragma unroll
    for (int i = 0; i < SEGLEN; i++) {
        size_t idx = base + (size_t)i * DDIM;
        float li = g_lam[idx];
        float si = g_su[idx];
        l[i] = li;
        v[i] = (1.0f - li) * si;
    }
    float h = cf;
    #pragma unroll
    for (int i = 0; i < SEGLEN; i++) { h = l[i] * h + v[i]; h_tile[i][d] = h; }
    float hr = cr;
    #pragma unroll
    for (int i = SEGLEN - 1; i >= 0; i--) {
        hr = l[i] * hr + v[i];
        h_tile[i][d] += hr;
    }
    __syncthreads();

    // warp w reduces row w (16 warps, 16 rows)
    const int w = d >> 5, lane = d & 31;
    float ss = 0.0f;
    #pragma unroll
    for (int j = 0; j < DDIM / 32; j++) {
        float x = h_tile[w][lane + j * 32];
        ss += x * x;
    }
    #pragma unroll
    for (int o = 16; o > 0; o >>= 1) ss += __shfl_xor_sync(0xffffffff, ss, o);
    if (lane == 0) scale_sm[w] = rsqrtf(ss * (1.0f / DDIM) + EPSV);
    __syncthreads();

    #pragma unroll
    for (int i = 0; i < SEGLEN; i++) {
        float hn = h_tile[i][d] * scale_sm[i] * g_gate[base + (size_t)i * DDIM];
        g_hnh[base + (size_t)i * DDIM] = __float2half_rn(hn);
    }
}

// ================= launch =================
extern "C" void kernel_launch(void* const* d_in, const int* in_sizes, int n_in,
                              void* d_out, int out_size)
{
    const float* x    = (const float*)d_in[0];
    const float* lb   = (const float*)d_in[1];
    const float* Win  = (const float*)d_in[2];
    const float* bin  = (const float*)d_in[3];
    const float* Wg   = (const float*)d_in[4];
    const float* bg   = (const float*)d_in[5];
    const float* Wout = (const float*)d_in[6];
    const float* bout = (const float*)d_in[7];
    float* out = (float*)d_out;

    __half *xh, *b1h, *b2h, *hnh;
    cudaGetSymbolAddress((void**)&xh,  g_xh);
    cudaGetSymbolAddress((void**)&b1h, g_b1h);
    cudaGetSymbolAddress((void**)&b2h, g_b2h);
    cudaGetSymbolAddress((void**)&hnh, g_hnh);

    cudaFuncSetAttribute(gemm_tc<0>, cudaFuncAttributeMaxDynamicSharedMemorySize, SMEM_REQ);
    cudaFuncSetAttribute(gemm_tc<1>, cudaFuncAttributeMaxDynamicSharedMemorySize, SMEM_REQ);

    convert_x_kernel<<<(MTOT * DDIM / 4) / 256, 256>>>(x);
    convert_w1_kernel<<<(N1 * DDIM) / 256, 256>>>(Win, Wg);
    convert_w2_kernel<<<(DDIM * DDIM) / 256, 256>>>(Wout);

    dim3 g1(N1 / BN, MTOT / BM);           // (12, 512)
    gemm_tc<0><<<g1, 256, SMEM_REQ>>>(xh, b1h, bin, bg, lb, nullptr);

    scan_phase1<<<SEGTOT / 256, 256>>>();
    scan_phase2<<<CHAINS / 256, 256>>>();
    scan3_rms_kernel<<<BATCH * NSEG, 512>>>();

    dim3 g2(DDIM / BN, MTOT / BM);         // (4, 512)
    gemm_tc<1><<<g2, 256, SMEM_REQ>>>(hnh, b2h, bout, nullptr, nullptr, out);
}

// round 14
// speedup vs baseline: 1.7740x; 1.0460x over previous
#include <cuda_runtime.h>
#include <cuda_fp16.h>
#include <stdint.h>
#include <math.h>

// Problem dims (fixed by the reference)
#define BATCH  16
#define NSEQ   4096
#define DDIM   512
#define MTOT   (BATCH*NSEQ)          // 65536 rows
#define CHAINS (BATCH*DDIM)          // 8192 scan chains
#define SEGLEN 16
#define NSEG   (NSEQ/SEGLEN)         // 256
#define SEGTOT (NSEG*CHAINS)         // 2097152
#define EPSV   1e-6f
#define N1     (3*DDIM)              // 1536
#define WSCALE 256.0f
#define WINV   (1.0f/256.0f)

// GEMM tiling: KC=32 chunks (2 k-steps per barrier), 80B padded rows
#define BM 128
#define BN 128
#define KC 32
#define ROWB 80                      // bytes per smem row (64 data + 16 pad)
#define ARR_BYTES (BM*ROWB)          // 10240
#define STAGE_BYTES (2*ARR_BYTES)    // 20480: [A | B]
#define NSTAGE 4
#define SMEM_REQ (NSTAGE*STAGE_BYTES) // 81920
#define NCHUNK (DDIM/KC)             // 16
#define NKSTEP (DDIM/16)             // 32

// ---------------- device scratch ----------------
__device__ __half g_xh  [MTOT*DDIM];          // x rounded to fp16
__device__ __half g_b1h [N1*DDIM];            // [n][k] (W_in|W_gate)*256 fp16
__device__ __half g_b2h [DDIM*DDIM];          // [n][k] W_out*256 fp16
__device__ float g_su  [MTOT*DDIM];
__device__ float g_lam [MTOT*DDIM];
__device__ float g_gate[MTOT*DDIM];
__device__ __half g_hnh [MTOT*DDIM];          // hn rounded to fp16
__device__ float g_aggA [SEGTOT];
__device__ float g_aggBf[SEGTOT];
__device__ float g_aggBr[SEGTOT];
__device__ float g_cf   [SEGTOT];
__device__ float g_cr   [SEGTOT];

__device__ __forceinline__ float sigm(float x) { return 1.0f / (1.0f + __expf(-x)); }
__device__ __forceinline__ uint32_t pack_h2(__half a, __half b) {
    return (uint32_t)__half_as_ushort(a) | ((uint32_t)__half_as_ushort(b) << 16);
}

// ---------------- PTX helpers ----------------
__device__ __forceinline__ void mma16816(float* c, const uint32_t* a, const uint32_t* b) {
    asm volatile(
        "mma.sync.aligned.m16n8k16.row.col.f32.f16.f16.f32 "
        "{%0,%1,%2,%3}, {%4,%5,%6,%7}, {%8,%9}, {%0,%1,%2,%3};"
        : "+f"(c[0]), "+f"(c[1]), "+f"(c[2]), "+f"(c[3])
        : "r"(a[0]), "r"(a[1]), "r"(a[2]), "r"(a[3]), "r"(b[0]), "r"(b[1]));
}
__device__ __forceinline__ void ldsm4(uint32_t* r, uint32_t addr) {
    asm volatile("ldmatrix.sync.aligned.m8n8.x4.shared.b16 {%0,%1,%2,%3}, [%4];"
                 : "=r"(r[0]), "=r"(r[1]), "=r"(r[2]), "=r"(r[3]) : "r"(addr));
}
__device__ __forceinline__ void cpasync16(uint32_t saddr, const void* g) {
    asm volatile("cp.async.cg.shared.global [%0], [%1], 16;" :: "r"(saddr), "l"(g));
}
__device__ __forceinline__ void cp_commit() { asm volatile("cp.async.commit_group;"); }
template<int N> __device__ __forceinline__ void cp_wait() {
    asm volatile("cp.async.wait_group %0;" :: "n"(N));
}

// ================= conversion kernels =================
__global__ __launch_bounds__(256) void convert_x_kernel(const float* __restrict__ X)
{
    int i = blockIdx.x * 256 + threadIdx.x;            // over float4s
    float4 v = ((const float4*)X)[i];
    uint2 u;
    u.x = pack_h2(__float2half_rn(v.x), __float2half_rn(v.y));
    u.y = pack_h2(__float2half_rn(v.z), __float2half_rn(v.w));
    ((uint2*)g_xh)[i] = u;
}
__global__ __launch_bounds__(256) void convert_w1_kernel(
    const float* __restrict__ Win, const float* __restrict__ Wg)
{
    int idx = blockIdx.x * 256 + threadIdx.x;          // [0, N1*DDIM)
    int n = idx / DDIM, k = idx % DDIM;
    float w = (n < 2 * DDIM) ? Win[(size_t)k * (2 * DDIM) + n]
                             : Wg [(size_t)k * DDIM + (n - 2 * DDIM)];
    g_b1h[idx] = __float2half_rn(w * WSCALE);
}
__global__ __launch_bounds__(256) void convert_w2_kernel(const float* __restrict__ Wout)
{
    int idx = blockIdx.x * 256 + threadIdx.x;          // [0, DDIM*DDIM)
    int n = idx / DDIM, k = idx % DDIM;
    g_b2h[idx] = __float2half_rn(Wout[(size_t)k * DDIM + n] * WSCALE);
}

// =================================================================================
// fp16 mma.sync GEMM. KC=32 stages: cp_wait + __syncthreads only every 2 k-steps
// (16 barriers instead of 32), register fragment double-buffer at k-step level.
// C = Ah(M x 512) * Bh(N x 512)^T, result scaled by 1/256 in epilogue.
// MODE 0: N=1536 fused [u|f|gate] epilogue.  MODE 1: N=512, +bias -> outp.
// =================================================================================
template<int MODE>
__global__ void __launch_bounds__(256, 2) gemm_tc(
    const __half* __restrict__ Ah, const __half* __restrict__ Bh,
    const float* __restrict__ bias_a, const float* __restrict__ bias_b,
    const float* __restrict__ lbp, float* __restrict__ outp)
{
    extern __shared__ __half tiles[];                  // 4 stages x 20KB
    const uint32_t sb = (uint32_t)__cvta_generic_to_shared(tiles);
    const int tid = threadIdx.x;
    const int r0 = blockIdx.y * BM;
    const int c0 = blockIdx.x * BN;

    float acc[4][4][4];
    #pragma unroll
    for (int i = 0; i < 4; i++)
        #pragma unroll
        for (int j = 0; j < 4; j++)
            #pragma unroll
            for (int q = 0; q < 4; q++) acc[i][j][q] = 0.0f;

    // cp.async mapping: per array 512 slots (row 0..127, seg 0..3 of 16B);
    // thread t handles slots t and t+256 (rows r and r+64, same seg).
    const int lrow = tid >> 2;           // 0..63
    const int lseg = tid & 3;            // 16B seg within 64B row data
    const size_t gA1 = (size_t)(r0 + lrow) * DDIM + lseg * 8;
    const size_t gA2 = gA1 + (size_t)64 * DDIM;
    const size_t gB1 = (size_t)(c0 + lrow) * DDIM + lseg * 8;
    const size_t gB2 = gB1 + (size_t)64 * DDIM;
    const uint32_t sOff1 = lrow * ROWB + lseg * 16;
    const uint32_t sOff2 = sOff1 + 64 * ROWB;

    // prologue: chunks 0..2 -> stages 0..2
    #pragma unroll
    for (int p = 0; p < 3; p++) {
        const uint32_t st = sb + (uint32_t)p * STAGE_BYTES;
        const int k0 = p * KC;
        cpasync16(st + sOff1,             Ah + gA1 + k0);
        cpasync16(st + sOff2,             Ah + gA2 + k0);
        cpasync16(st + ARR_BYTES + sOff1, Bh + gB1 + k0);
        cpasync16(st + ARR_BYTES + sOff2, Bh + gB2 + k0);
        cp_commit();
    }

    const int lane = tid & 31, wid = tid >> 5;
    const int wm = wid >> 2, wn = wid & 3;
    const int sub = lane >> 3, lr = lane & 7;
    // ksel k-step offset = +32B within the 80B row
    const uint32_t boBase = (uint32_t)(wn * 32 + lr + (sub >> 1) * 8) * ROWB
                          + (uint32_t)(sub & 1) * 16;
    const uint32_t aoBase = (uint32_t)(wm * 64 + lr + (sub & 1) * 8) * ROWB
                          + (uint32_t)(sub >> 1) * 16;

    uint32_t aF[2][4][4], bF[2][4][2];

    cp_wait<1>();          // chunks 0,1 resident
    __syncthreads();
    {   // frags for k-step 0 (stage 0, ksel 0)
        const uint32_t st = sb;
        #pragma unroll
        for (int p = 0; p < 2; p++) {
            uint32_t t4[4];
            ldsm4(t4, st + ARR_BYTES + boBase + (uint32_t)(p * 16) * ROWB);
            bF[0][2*p][0] = t4[0]; bF[0][2*p][1] = t4[1];
            bF[0][2*p+1][0] = t4[2]; bF[0][2*p+1][1] = t4[3];
        }
        #pragma unroll
        for (int mi = 0; mi < 4; mi++)
            ldsm4(aF[0][mi], st + aoBase + (uint32_t)(mi * 16) * ROWB);
    }

    for (int kk = 0; kk < NKSTEP; kk++) {
        const int cur = kk & 1, nxt = cur ^ 1;
        if (cur == 0) {
            if (kk > 0) {      // chunk boundary: stages kk/2, kk/2+1 resident
                cp_wait<1>();
                __syncthreads();
            }
            const int cn = (kk >> 1) + 3;
            if (cn < NCHUNK) {
                const uint32_t stn = sb + (uint32_t)(cn & 3) * STAGE_BYTES;
                const int k0 = cn * KC;
                cpasync16(stn + sOff1,             Ah + gA1 + k0);
                cpasync16(stn + sOff2,             Ah + gA2 + k0);
                cpasync16(stn + ARR_BYTES + sOff1, Bh + gB1 + k0);
                cpasync16(stn + ARR_BYTES + sOff2, Bh + gB2 + k0);
            }
            cp_commit();
        }
        // prefetch frags for k-step kk+1
        if (kk + 1 < NKSTEP) {
            const uint32_t st = sb + (uint32_t)(((kk + 1) >> 1) & 3) * STAGE_BYTES;
            const uint32_t ko = (uint32_t)((kk + 1) & 1) * 32;
            #pragma unroll
            for (int p = 0; p < 2; p++) {
                uint32_t t4[4];
                ldsm4(t4, st + ARR_BYTES + boBase + ko + (uint32_t)(p * 16) * ROWB);
                bF[nxt][2*p][0] = t4[0]; bF[nxt][2*p][1] = t4[1];
                bF[nxt][2*p+1][0] = t4[2]; bF[nxt][2*p+1][1] = t4[3];
            }
            #pragma unroll
            for (int mi = 0; mi < 4; mi++)
                ldsm4(aF[nxt][mi], st + aoBase + ko + (uint32_t)(mi * 16) * ROWB);
        }
        // mmas for k-step kk (fragments loaded previous iteration)
        #pragma unroll
        for (int mi = 0; mi < 4; mi++)
            #pragma unroll
            for (int ni = 0; ni < 4; ni++)
                mma16816(acc[mi][ni], aF[cur][mi], bF[cur][ni]);
    }

    // -------- epilogue (descale by 1/256, then bias + activations) --------
    const int g = lane >> 2, t = lane & 3;
    float lb = 0.0f;
    if (MODE == 0) lb = lbp[0];

    #pragma unroll
    for (int mi = 0; mi < 4; mi++) {
        const int m0 = r0 + wm * 64 + mi * 16 + g;
        #pragma unroll
        for (int ni = 0; ni < 4; ni++) {
            const int nc = c0 + wn * 32 + ni * 8 + t * 2;
            float p0 = acc[mi][ni][0] * WINV, p1 = acc[mi][ni][1] * WINV;
            float p2 = acc[mi][ni][2] * WINV, p3 = acc[mi][ni][3] * WINV;
            if (MODE == 1) {
                const float b0 = bias_a[nc], b1 = bias_a[nc + 1];
                *(float2*)&outp[(size_t)m0 * DDIM + nc]       = make_float2(p0 + b0, p1 + b1);
                *(float2*)&outp[(size_t)(m0+8) * DDIM + nc]   = make_float2(p2 + b0, p3 + b1);
            } else {
                const int reg = nc >> 9;           // 0=u, 1=f, 2=gate
                const int lc = nc & 511;
                float b0, b1; float* dst;
                if (reg < 2) { b0 = bias_a[nc]; b1 = bias_a[nc + 1]; }
                else         { b0 = bias_b[lc]; b1 = bias_b[lc + 1]; }
                p0 += b0; p1 += b1; p2 += b0; p3 += b1;
                float o0, o1, o2, o3;
                if (reg == 0) {
                    o0 = p0 * sigm(p0); o1 = p1 * sigm(p1);
                    o2 = p2 * sigm(p2); o3 = p3 * sigm(p3);
                    dst = g_su;
                } else if (reg == 1) {
                    const float w = 1.0f - lb;
                    o0 = lb + w * sigm(p0); o1 = lb + w * sigm(p1);
                    o2 = lb + w * sigm(p2); o3 = lb + w * sigm(p3);
                    dst = g_lam;
                } else {
                    o0 = sigm(p0); o1 = sigm(p1); o2 = sigm(p2); o3 = sigm(p3);
                    dst = g_gate;
                }
                *(float2*)&dst[(size_t)m0 * DDIM + lc]     = make_float2(o0, o1);
                *(float2*)&dst[(size_t)(m0+8) * DDIM + lc] = make_float2(o2, o3);
            }
        }
    }
}

// ================= scan path =================
__global__ __launch_bounds__(256) void scan_phase1()
{
    int tt = blockIdx.x * blockDim.x + threadIdx.x;
    int chain = tt % CHAINS;
    int seg   = tt / CHAINS;
    int d = chain % DDIM, b = chain / DDIM;
    size_t base = ((size_t)(b * NSEQ + seg * SEGLEN)) * DDIM + d;

    float l[SEGLEN], v[SEGLEN];
    #pragma unroll
    for (int i = 0; i < SEGLEN; i++) {
        size_t idx = base + (size_t)i * DDIM;
        float li = g_lam[idx];
        float si = g_su[idx];
        l[i] = li;
        v[i] = (1.0f - li) * si;
    }
    float h = 0.0f, P = 1.0f;
    #pragma unroll
    for (int i = 0; i < SEGLEN; i++) { h = l[i] * h + v[i]; P *= l[i]; }
    float hr = 0.0f;
    #pragma unroll
    for (int i = SEGLEN - 1; i >= 0; i--) hr = l[i] * hr + v[i];

    size_t aidx = (size_t)seg * CHAINS + chain;
    g_aggA [aidx] = P;
    g_aggBf[aidx] = h;
    g_aggBr[aidx] = hr;
}
__global__ __launch_bounds__(256) void scan_phase2()
{
    int c = blockIdx.x * blockDim.x + threadIdx.x;
    float carry = 0.0f;
    #pragma unroll 8
    for (int s = 0; s < NSEG; s++) {
        size_t a = (size_t)s * CHAINS + c;
        g_cf[a] = carry;
        carry = g_aggA[a] * carry + g_aggBf[a];
    }
    carry = 0.0f;
    #pragma unroll 8
    for (int s = NSEG - 1; s >= 0; s--) {
        size_t a = (size_t)s * CHAINS + c;
        g_cr[a] = carry;
        carry = g_aggA[a] * carry + g_aggBr[a];
    }
}
// =================================================================================
// Fused scan_phase3 + SimpleRMSNorm + gate. h stays in a 32KB smem tile.
// =================================================================================
__global__ __launch_bounds__(512) void scan3_rms_kernel()
{
    __shared__ float h_tile[SEGLEN][DDIM];     // 32 KB
    __shared__ float scale_sm[SEGLEN];
    const int blk = blockIdx.x;                // b*NSEG + seg
    const int b = blk / NSEG, seg = blk % NSEG;
    const int d = threadIdx.x;
    const int chain = b * DDIM + d;
    const size_t aidx = (size_t)seg * CHAINS + chain;
    const float cf = g_cf[aidx];
    const float cr = g_cr[aidx];
    const size_t base = ((size_t)(b * NSEQ + seg * SEGLEN)) * DDIM + d;

    float l[SEGLEN], v[SEGLEN];
    #pragma unroll
    for (int i = 0; i < SEGLEN; i++) {
        size_t idx = base + (size_t)i * DDIM;
        float li = g_lam[idx];
        float si = g_su[idx];
        l[i] = li;
        v[i] = (1.0f - li) * si;
    }
    float h = cf;
    #pragma unroll
    for (int i = 0; i < SEGLEN; i++) { h = l[i] * h + v[i]; h_tile[i][d] = h; }
    float hr = cr;
    #pragma unroll
    for (int i = SEGLEN - 1; i >= 0; i--) {
        hr = l[i] * hr + v[i];
        h_tile[i][d] += hr;
    }
    __syncthreads();

    const int w = d >> 5, lane = d & 31;
    float ss = 0.0f;
    #pragma unroll
    for (int j = 0; j < DDIM / 32; j++) {
        float x = h_tile[w][lane + j * 32];
        ss += x * x;
    }
    #pragma unroll
    for (int o = 16; o > 0; o >>= 1) ss += __shfl_xor_sync(0xffffffff, ss, o);
    if (lane == 0) scale_sm[w] = rsqrtf(ss * (1.0f / DDIM) + EPSV);
    __syncthreads();

    #pragma unroll
    for (int i = 0; i < SEGLEN; i++) {
        float hn = h_tile[i][d] * scale_sm[i] * g_gate[base + (size_t)i * DDIM];
        g_hnh[base + (size_t)i * DDIM] = __float2half_rn(hn);
    }
}

// ================= launch =================
extern "C" void kernel_launch(void* const* d_in, const int* in_sizes, int n_in,
                              void* d_out, int out_size)
{
    const float* x    = (const float*)d_in[0];
    const float* lb   = (const float*)d_in[1];
    const float* Win  = (const float*)d_in[2];
    const float* bin  = (const float*)d_in[3];
    const float* Wg   = (const float*)d_in[4];
    const float* bg   = (const float*)d_in[5];
    const float* Wout = (const float*)d_in[6];
    const float* bout = (const float*)d_in[7];
    float* out = (float*)d_out;

    __half *xh, *b1h, *b2h, *hnh;
    cudaGetSymbolAddress((void**)&xh,  g_xh);
    cudaGetSymbolAddress((void**)&b1h, g_b1h);
    cudaGetSymbolAddress((void**)&b2h, g_b2h);
    cudaGetSymbolAddress((void**)&hnh, g_hnh);

    cudaFuncSetAttribute(gemm_tc<0>, cudaFuncAttributeMaxDynamicSharedMemorySize, SMEM_REQ);
    cudaFuncSetAttribute(gemm_tc<1>, cudaFuncAttributeMaxDynamicSharedMemorySize, SMEM_REQ);

    convert_x_kernel<<<(MTOT * DDIM / 4) / 256, 256>>>(x);
    convert_w1_kernel<<<(N1 * DDIM) / 256, 256>>>(Win, Wg);
    convert_w2_kernel<<<(DDIM * DDIM) / 256, 256>>>(Wout);

    dim3 g1(N1 / BN, MTOT / BM);           // (12, 512)
    gemm_tc<0><<<g1, 256, SMEM_REQ>>>(xh, b1h, bin, bg, lb, nullptr);

    scan_phase1<<<SEGTOT / 256, 256>>>();
    scan_phase2<<<CHAINS / 256, 256>>>();
    scan3_rms_kernel<<<BATCH * NSEG, 512>>>();

    dim3 g2(DDIM / BN, MTOT / BM);         // (4, 512)
    gemm_tc<1><<<g2, 256, SMEM_REQ>>>(hnh, b2h, bout, nullptr, nullptr, out);
}